// round 2
// baseline (speedup 1.0000x reference)
#include <cuda_runtime.h>
#include <math.h>
#include <float.h>

#define BB 4
#define TT 2048
#define DD 2048
#define HH 16
#define GG 4
#define KKD 128
#define NTOK (BB*TT)          /* 8192 */
#define QW (HH*KKD)           /* 2048 */
#define KVW (GG*KKD)          /* 512  */

// ---------------- scratch (static device globals; no allocation) ----------------
__device__ float g_q[(size_t)NTOK*QW];
__device__ float g_k[(size_t)NTOK*KVW];
__device__ float g_v[(size_t)NTOK*KVW];
__device__ float g_attn[(size_t)NTOK*QW];
__device__ int   g_pos[NTOK];

// ---------------- positions from sorted segment ids ----------------
__global__ void pos_kernel(const int* __restrict__ seg) {
    int idx = blockIdx.x * blockDim.x + threadIdx.x;
    if (idx >= NTOK) return;
    int b = idx / TT, t = idx % TT;
    const int* s = seg + b * TT;
    int v = s[t];
    int lo = 0, hi = t;
    while (lo < hi) { int mid = (lo + hi) >> 1; if (s[mid] < v) lo = mid + 1; else hi = mid; }
    g_pos[idx] = t - lo;
}

// ---------------- fp32 SGEMM: C[M,N] = A[M,K] * B[K,N], all dims % 128 == 0 ----
__global__ __launch_bounds__(256) void sgemm_kernel(
    const float* __restrict__ A, const float* __restrict__ B, float* __restrict__ C,
    int M, int N, int Kd)
{
    __shared__ float As[16][128];
    __shared__ float Bs[16][128];
    int tid = threadIdx.x;
    int tx = tid & 15, ty = tid >> 4;
    int row0 = blockIdx.y * 128, col0 = blockIdx.x * 128;

    float acc[8][8];
#pragma unroll
    for (int i = 0; i < 8; i++)
#pragma unroll
        for (int j = 0; j < 8; j++) acc[i][j] = 0.f;

    const float* Ap = A + (size_t)row0 * Kd;
    const float* Bp = B + col0;

    for (int k0 = 0; k0 < Kd; k0 += 16) {
#pragma unroll
        for (int i = 0; i < 2; i++) {
            int idx = tid + i * 256;
            int ar = idx >> 2, ac4 = idx & 3;
            float4 va = *(const float4*)(Ap + (size_t)ar * Kd + k0 + ac4 * 4);
            As[ac4 * 4 + 0][ar] = va.x;
            As[ac4 * 4 + 1][ar] = va.y;
            As[ac4 * 4 + 2][ar] = va.z;
            As[ac4 * 4 + 3][ar] = va.w;
        }
#pragma unroll
        for (int i = 0; i < 2; i++) {
            int idx = tid + i * 256;
            int br = idx >> 5, bc = idx & 31;
            *(float4*)(&Bs[br][bc * 4]) = *(const float4*)(Bp + (size_t)(k0 + br) * N + bc * 4);
        }
        __syncthreads();
#pragma unroll
        for (int kk = 0; kk < 16; kk++) {
            float a[8], b[8];
#pragma unroll
            for (int i = 0; i < 8; i++) a[i] = As[kk][ty * 8 + i];
#pragma unroll
            for (int j = 0; j < 8; j++) b[j] = Bs[kk][tx * 8 + j];
#pragma unroll
            for (int i = 0; i < 8; i++)
#pragma unroll
                for (int j = 0; j < 8; j++) acc[i][j] += a[i] * b[j];
        }
        __syncthreads();
    }

#pragma unroll
    for (int i = 0; i < 8; i++) {
        float* cp = C + (size_t)(row0 + ty * 8 + i) * N + col0 + tx * 8;
        float4 v0 = make_float4(acc[i][0], acc[i][1], acc[i][2], acc[i][3]);
        float4 v1 = make_float4(acc[i][4], acc[i][5], acc[i][6], acc[i][7]);
        *(float4*)cp = v0;
        *(float4*)(cp + 4) = v1;
    }
}

// ---------------- fused RMSNorm + RoPE (per (token, head) row of 128) ----------
__global__ void normrope_kernel(float* __restrict__ x, const float* __restrict__ scale, int heads) {
    int warp = (blockIdx.x * blockDim.x + threadIdx.x) >> 5;
    int lane = threadIdx.x & 31;
    int token = warp / heads;
    int head = warp % heads;
    float* p = x + (size_t)token * heads * KKD + head * KKD;

    float4 v = *(float4*)(p + lane * 4);
    float ss = v.x * v.x + v.y * v.y + v.z * v.z + v.w * v.w;
#pragma unroll
    for (int o = 16; o > 0; o >>= 1) ss += __shfl_xor_sync(0xffffffffu, ss, o);
    float inv = rsqrtf(ss * (1.0f / 128.0f) + 1e-6f);
    float4 sc = *(const float4*)(scale + lane * 4);
    float vv[4];
    vv[0] = v.x * inv * sc.x; vv[1] = v.y * inv * sc.y;
    vv[2] = v.z * inv * sc.z; vv[3] = v.w * inv * sc.w;

    float pf = (float)g_pos[token];
    float out[4];
#pragma unroll
    for (int c = 0; c < 4; c++) {
        int k = lane * 4 + c;
        int j = k & 63;
        // inv_freq = exp(-ln(10000) * j/64)
        float invf = expf(-9.210340371976184f * ((float)j * (1.0f / 64.0f)));
        float sn, cs;
        sincosf(pf * invf, &sn, &cs);
        float partner = __shfl_xor_sync(0xffffffffu, vv[c], 16);
        out[c] = (k < 64) ? (vv[c] * cs - partner * sn) : (vv[c] * cs + partner * sn);
    }
    *(float4*)(p + lane * 4) = make_float4(out[0], out[1], out[2], out[3]);
}

// ---------------- flash attention with segment-causal mask ---------------------
// BM=BN=64, 256 threads (16x16). Thread (tx,ty): S cols tx+jj*16 (jj<4),
// O cols tx+jj*16 (jj<8), rows ty*4+ii (ii<4).
#define KV_STRIDE 129
#define P_STRIDE 65
#define ATT_SMEM_BYTES ((64*128 + 64*KV_STRIDE + 64*P_STRIDE) * 4 + 64 * 4)

__global__ __launch_bounds__(256) void attn_kernel() {
    extern __shared__ float sm[];
    float* Qs = sm;                         // 64 x 128
    float* KVs = Qs + 64 * 128;             // 64 x 129
    float* Ps = KVs + 64 * KV_STRIDE;       // 64 x 65
    int* Sst = (int*)(Ps + 64 * P_STRIDE);  // 64

    const int tid = threadIdx.x;
    const int tx = tid & 15, ty = tid >> 4;
    const int b = blockIdx.z, h = blockIdx.y;
    const int t0 = blockIdx.x * 64;
    const int g = h >> 2;  // GQA group (R = 4)
    const float scale = 0.08838834764831845f;  // 128^-0.5
    const float NEG = -1e30f;

    // load Q tile [64 x 128]
#pragma unroll
    for (int i = 0; i < 8; i++) {
        int r = tid >> 2;
        int c4 = (tid & 3) + i * 4;
        *(float4*)(Qs + r * 128 + c4 * 4) =
            *(const float4*)(g_q + (size_t)(b * TT + t0 + r) * QW + h * KKD + c4 * 4);
    }
    if (tid < 64) {
        int t = t0 + tid;
        Sst[tid] = t - g_pos[b * TT + t];
    }
    __syncthreads();

    const int s_begin = Sst[0] & ~63;  // seg_start is nondecreasing -> min at row 0
    int my_start[4];
#pragma unroll
    for (int ii = 0; ii < 4; ii++) my_start[ii] = Sst[ty * 4 + ii];

    float m[4], l[4], O[4][8];
#pragma unroll
    for (int ii = 0; ii < 4; ii++) {
        m[ii] = NEG; l[ii] = 0.f;
#pragma unroll
        for (int jj = 0; jj < 8; jj++) O[ii][jj] = 0.f;
    }

    for (int s0 = s_begin; s0 <= t0; s0 += 64) {
        // ---- load K tile into KVs ----
#pragma unroll
        for (int i = 0; i < 8; i++) {
            int r = tid >> 2;
            int c4 = (tid & 3) + i * 4;
            float4 vv = *(const float4*)(g_k + (size_t)(b * TT + s0 + r) * KVW + g * KKD + c4 * 4);
            float* dst = KVs + r * KV_STRIDE + c4 * 4;
            dst[0] = vv.x; dst[1] = vv.y; dst[2] = vv.z; dst[3] = vv.w;
        }
        __syncthreads();

        // ---- S = Q K^T ----
        float acc[4][4];
#pragma unroll
        for (int ii = 0; ii < 4; ii++)
#pragma unroll
            for (int jj = 0; jj < 4; jj++) acc[ii][jj] = 0.f;
#pragma unroll 4
        for (int k = 0; k < 128; k++) {
            float qv[4], kv[4];
#pragma unroll
            for (int ii = 0; ii < 4; ii++) qv[ii] = Qs[(ty * 4 + ii) * 128 + k];
#pragma unroll
            for (int jj = 0; jj < 4; jj++) kv[jj] = KVs[(tx + jj * 16) * KV_STRIDE + k];
#pragma unroll
            for (int ii = 0; ii < 4; ii++)
#pragma unroll
                for (int jj = 0; jj < 4; jj++) acc[ii][jj] += qv[ii] * kv[jj];
        }

        // ---- mask + online softmax ----
#pragma unroll
        for (int ii = 0; ii < 4; ii++) {
            int t = t0 + ty * 4 + ii;
            float rmax = NEG;
#pragma unroll
            for (int jj = 0; jj < 4; jj++) {
                int s = s0 + tx + jj * 16;
                bool valid = (s <= t) && (s >= my_start[ii]);
                float val = valid ? acc[ii][jj] * scale : NEG;
                acc[ii][jj] = val;
                rmax = fmaxf(rmax, val);
            }
#pragma unroll
            for (int o = 1; o < 16; o <<= 1)
                rmax = fmaxf(rmax, __shfl_xor_sync(0xffffffffu, rmax, o));
            float mn = fmaxf(m[ii], rmax);
            float corr = __expf(m[ii] - mn);  // 0 - 0 when both NEG -> 1; ok
            m[ii] = mn;
            l[ii] *= corr;
#pragma unroll
            for (int jj = 0; jj < 8; jj++) O[ii][jj] *= corr;
            float rsum = 0.f;
#pragma unroll
            for (int jj = 0; jj < 4; jj++) {
                int s = s0 + tx + jj * 16;
                bool valid = (s <= t) && (s >= my_start[ii]);
                float pv = valid ? __expf(acc[ii][jj] - mn) : 0.f;
                rsum += pv;
                Ps[(ty * 4 + ii) * P_STRIDE + tx + jj * 16] = pv;
            }
#pragma unroll
            for (int o = 1; o < 16; o <<= 1)
                rsum += __shfl_xor_sync(0xffffffffu, rsum, o);
            l[ii] += rsum;
        }
        __syncthreads();  // all readers of K done, all Ps written

        // ---- load V tile into KVs (reuse buffer) ----
#pragma unroll
        for (int i = 0; i < 8; i++) {
            int r = tid >> 2;
            int c4 = (tid & 3) + i * 4;
            float4 vv = *(const float4*)(g_v + (size_t)(b * TT + s0 + r) * KVW + g * KKD + c4 * 4);
            float* dst = KVs + r * KV_STRIDE + c4 * 4;
            dst[0] = vv.x; dst[1] = vv.y; dst[2] = vv.z; dst[3] = vv.w;
        }
        __syncthreads();

        // ---- O += P V ----
#pragma unroll 2
        for (int s = 0; s < 64; s++) {
            float pr[4], vr[8];
#pragma unroll
            for (int ii = 0; ii < 4; ii++) pr[ii] = Ps[(ty * 4 + ii) * P_STRIDE + s];
#pragma unroll
            for (int jj = 0; jj < 8; jj++) vr[jj] = KVs[s * KV_STRIDE + tx + jj * 16];
#pragma unroll
            for (int ii = 0; ii < 4; ii++)
#pragma unroll
                for (int jj = 0; jj < 8; jj++) O[ii][jj] += pr[ii] * vr[jj];
        }
        __syncthreads();  // before next iteration overwrites KVs / Ps
    }

    // ---- epilogue: normalize + store ----
#pragma unroll
    for (int ii = 0; ii < 4; ii++) {
        float invl = 1.0f / l[ii];
        float* dst = g_attn + (size_t)(b * TT + t0 + ty * 4 + ii) * QW + h * KKD;
#pragma unroll
        for (int jj = 0; jj < 8; jj++) dst[tx + jj * 16] = O[ii][jj] * invl;
    }
}

// ---------------- launch ----------------
extern "C" void kernel_launch(void* const* d_in, const int* in_sizes, int n_in,
                              void* d_out, int out_size) {
    const float* hidden  = (const float*)d_in[0];
    const float* wq      = (const float*)d_in[1];
    const float* wk      = (const float*)d_in[2];
    const float* wv      = (const float*)d_in[3];
    const float* wo      = (const float*)d_in[4];
    const float* q_scale = (const float*)d_in[5];
    const float* k_scale = (const float*)d_in[6];
    const int*   seg     = (const int*)d_in[7];
    float* out = (float*)d_out;

    float *q, *k, *v, *attn;
    cudaGetSymbolAddress((void**)&q, g_q);
    cudaGetSymbolAddress((void**)&k, g_k);
    cudaGetSymbolAddress((void**)&v, g_v);
    cudaGetSymbolAddress((void**)&attn, g_attn);

    cudaFuncSetAttribute(attn_kernel, cudaFuncAttributeMaxDynamicSharedMemorySize,
                         ATT_SMEM_BYTES);

    pos_kernel<<<NTOK / 256, 256>>>(seg);

    sgemm_kernel<<<dim3(QW / 128, NTOK / 128), 256>>>(hidden, wq, q, NTOK, QW, DD);
    sgemm_kernel<<<dim3(KVW / 128, NTOK / 128), 256>>>(hidden, wk, k, NTOK, KVW, DD);
    sgemm_kernel<<<dim3(KVW / 128, NTOK / 128), 256>>>(hidden, wv, v, NTOK, KVW, DD);

    normrope_kernel<<<(NTOK * HH) / 8, 256>>>(q, q_scale, HH);
    normrope_kernel<<<(NTOK * GG) / 8, 256>>>(k, k_scale, GG);

    attn_kernel<<<dim3(TT / 64, HH, BB), 256, ATT_SMEM_BYTES>>>();

    sgemm_kernel<<<dim3(DD / 128, NTOK / 128), 256>>>(attn, wo, out, NTOK, DD, QW);
}

// round 4
// speedup vs baseline: 1.8567x; 1.8567x over previous
#include <cuda_runtime.h>
#include <cuda_bf16.h>
#include <math.h>
#include <stdint.h>

#define BB 4
#define TT 2048
#define DD 2048
#define HH 16
#define GG 4
#define KKD 128
#define NTOK (BB*TT)          /* 8192 */
#define QW (HH*KKD)           /* 2048 */
#define KVW (GG*KKD)          /* 512  */

// ---------------- scratch (static device globals; no allocation) ----------------
__device__ float g_q[(size_t)NTOK*QW];
__device__ float g_k[(size_t)NTOK*KVW];
__device__ float g_v[(size_t)NTOK*KVW];
__device__ float g_attn[(size_t)NTOK*QW];
__device__ int   g_pos[NTOK];

__device__ __nv_bfloat16 g_hid_hi[(size_t)NTOK*DD];
__device__ __nv_bfloat16 g_hid_lo[(size_t)NTOK*DD];
__device__ __nv_bfloat16 g_att_hi[(size_t)NTOK*QW];
__device__ __nv_bfloat16 g_att_lo[(size_t)NTOK*QW];
__device__ __nv_bfloat16 g_wq_hi[(size_t)QW*DD];
__device__ __nv_bfloat16 g_wq_lo[(size_t)QW*DD];
__device__ __nv_bfloat16 g_wk_hi[(size_t)KVW*DD];
__device__ __nv_bfloat16 g_wk_lo[(size_t)KVW*DD];
__device__ __nv_bfloat16 g_wv_hi[(size_t)KVW*DD];
__device__ __nv_bfloat16 g_wv_lo[(size_t)KVW*DD];
__device__ __nv_bfloat16 g_wo_hi[(size_t)DD*QW];
__device__ __nv_bfloat16 g_wo_lo[(size_t)DD*QW];

// ---------------- base-ISA PTX helpers (NO sm_103a-only features) --------------
__device__ __forceinline__ uint32_t smem_u32(const void* p) {
    uint32_t a;
    asm("{ .reg .u64 t; cvta.to.shared.u64 t, %1; cvt.u32.u64 %0, t; }" : "=r"(a) : "l"(p));
    return a;
}
__device__ __forceinline__ void cp16(uint32_t saddr, const void* g) {
    asm volatile("cp.async.cg.shared.global [%0], [%1], 16;" :: "r"(saddr), "l"(g) : "memory");
}
__device__ __forceinline__ void ldm_x4(uint32_t& r0, uint32_t& r1, uint32_t& r2, uint32_t& r3, uint32_t a) {
    asm volatile("ldmatrix.sync.aligned.m8n8.x4.shared.b16 {%0,%1,%2,%3}, [%4];"
                 : "=r"(r0), "=r"(r1), "=r"(r2), "=r"(r3) : "r"(a));
}
__device__ __forceinline__ void ldm_x2(uint32_t& r0, uint32_t& r1, uint32_t a) {
    asm volatile("ldmatrix.sync.aligned.m8n8.x2.shared.b16 {%0,%1}, [%2];"
                 : "=r"(r0), "=r"(r1) : "r"(a));
}
__device__ __forceinline__ void mma16816(float* d, const uint32_t* a, const uint32_t* b) {
    asm volatile(
        "mma.sync.aligned.m16n8k16.row.col.f32.bf16.bf16.f32 "
        "{%0,%1,%2,%3}, {%4,%5,%6,%7}, {%8,%9}, {%0,%1,%2,%3};"
        : "+f"(d[0]), "+f"(d[1]), "+f"(d[2]), "+f"(d[3])
        : "r"(a[0]), "r"(a[1]), "r"(a[2]), "r"(a[3]), "r"(b[0]), "r"(b[1]));
}

// ---------------- positions from sorted segment ids ----------------
__global__ void pos_kernel(const int* __restrict__ seg) {
    int idx = blockIdx.x * blockDim.x + threadIdx.x;
    if (idx >= NTOK) return;
    int b = idx / TT, t = idx % TT;
    const int* s = seg + b * TT;
    int v = s[t];
    int lo = 0, hi = t;
    while (lo < hi) { int mid = (lo + hi) >> 1; if (s[mid] < v) lo = mid + 1; else hi = mid; }
    g_pos[idx] = t - lo;
}

// ---------------- elementwise fp32 -> (hi, lo) bf16 split ----------------
__global__ void split_kernel(const float* __restrict__ x,
                             __nv_bfloat16* __restrict__ hi,
                             __nv_bfloat16* __restrict__ lo, int n4) {
    int i = blockIdx.x * blockDim.x + threadIdx.x;
    if (i >= n4) return;
    float4 v = ((const float4*)x)[i];
    __nv_bfloat16 h0 = __float2bfloat16(v.x);
    __nv_bfloat16 h1 = __float2bfloat16(v.y);
    __nv_bfloat16 h2 = __float2bfloat16(v.z);
    __nv_bfloat16 h3 = __float2bfloat16(v.w);
    __nv_bfloat162 ha, hb, la, lb;
    ha.x = h0; ha.y = h1; hb.x = h2; hb.y = h3;
    la.x = __float2bfloat16(v.x - __bfloat162float(h0));
    la.y = __float2bfloat16(v.y - __bfloat162float(h1));
    lb.x = __float2bfloat16(v.z - __bfloat162float(h2));
    lb.y = __float2bfloat16(v.w - __bfloat162float(h3));
    ((__nv_bfloat162*)hi)[2*i] = ha; ((__nv_bfloat162*)hi)[2*i+1] = hb;
    ((__nv_bfloat162*)lo)[2*i] = la; ((__nv_bfloat162*)lo)[2*i+1] = lb;
}

// ---------------- weight transpose + split: W[Rk,N] -> T[N,Rk] hi/lo bf16 -----
__global__ void tsplit_kernel(const float* __restrict__ W,
                              __nv_bfloat16* __restrict__ hi,
                              __nv_bfloat16* __restrict__ lo, int Rk, int N) {
    __shared__ float tile[32][33];
    int tx = threadIdx.x;
    int x = blockIdx.x * 32 + tx;     // N dim
    int y0 = blockIdx.y * 32;         // Rk dim
    for (int i = threadIdx.y; i < 32; i += 8)
        tile[i][tx] = W[(size_t)(y0 + i) * N + x];
    __syncthreads();
    int k = y0 + tx;
    for (int i = threadIdx.y; i < 32; i += 8) {
        int n = blockIdx.x * 32 + i;
        float val = tile[tx][i];
        __nv_bfloat16 h = __float2bfloat16(val);
        hi[(size_t)n * Rk + k] = h;
        lo[(size_t)n * Rk + k] = __float2bfloat16(val - __bfloat162float(h));
    }
}

// ---------------- 3xBF16 GEMM via mma.sync (base ISA, runs as HMMA) ----------
// A (hi/lo): [Mtot, Kd] bf16 row-major; B (hi/lo): [Ntot, Kd] bf16 row-major.
// C[M,N] = sum_k A[m,k]*B[n,k], fp32 accumulate.
// Tile 128x128, BK=32, 256 threads = 8 warps in 2(M) x 4(N); warp tile 64x32.
#define ROWB 80                 /* smem row stride in bytes (40 bf16), conflict-free */
#define BUFB 10240              /* 128 rows * 80B */
#define GSTAGE (4*BUFB)         /* Ahi,Alo,Bhi,Blo */
#define GSM (2*GSTAGE)          /* 81920 B */

__global__ __launch_bounds__(256, 1) void mma_gemm_kernel(
    const __nv_bfloat16* __restrict__ Ahi, const __nv_bfloat16* __restrict__ Alo,
    const __nv_bfloat16* __restrict__ Bhi, const __nv_bfloat16* __restrict__ Blo,
    float* __restrict__ C, int Ntot, int Kd)
{
    extern __shared__ __align__(128) char smbuf[];
    const int tid = threadIdx.x;
    const int wid = tid >> 5, lane = tid & 31;
    const int warp_m = wid >> 2, warp_n = wid & 3;
    const int row0 = blockIdx.y * 128, col0 = blockIdx.x * 128;
    const uint32_t smb = smem_u32(smbuf);

    const __nv_bfloat16* bases[4] = {
        Ahi + (size_t)row0 * Kd, Alo + (size_t)row0 * Kd,
        Bhi + (size_t)col0 * Kd, Blo + (size_t)col0 * Kd };

    float acc[4][4][4];
#pragma unroll
    for (int i = 0; i < 4; i++)
#pragma unroll
        for (int j = 0; j < 4; j++)
#pragma unroll
            for (int c = 0; c < 4; c++) acc[i][j][c] = 0.f;

    const int T = Kd >> 5;

    // per-thread cp.async slots: 8 chunks of 16B
    int ld_buf[8], ld_row[8], ld_c[8];
#pragma unroll
    for (int i = 0; i < 8; i++) {
        int id = tid + (i << 8);
        ld_buf[i] = id >> 9;
        int rem = id & 511;
        ld_row[i] = rem >> 2;
        ld_c[i] = rem & 3;
    }

#define LOAD_STAGE(t, s) do {                                                   \
    int k0_ = (t) << 5;                                                         \
    _Pragma("unroll")                                                           \
    for (int i_ = 0; i_ < 8; i_++) {                                            \
        uint32_t sa = smb + (s) * GSTAGE + ld_buf[i_] * BUFB +                  \
                      ld_row[i_] * ROWB + ld_c[i_] * 16;                        \
        const __nv_bfloat16* g = bases[ld_buf[i_]] +                            \
            (size_t)ld_row[i_] * Kd + k0_ + ld_c[i_] * 8;                       \
        cp16(sa, g);                                                            \
    }                                                                           \
    asm volatile("cp.async.commit_group;" ::: "memory");                        \
} while (0)

    // fragment lane addressing (bytes)
    const uint32_t aoff = (uint32_t)((warp_m * 64 + (lane & 15)) * ROWB + ((lane >> 4) << 3) * 2);
    const uint32_t boff = (uint32_t)((warp_n * 32 + (lane & 7)) * ROWB + (((lane >> 3) & 1) << 3) * 2);

    LOAD_STAGE(0, 0);

    for (int t = 0; t < T; t++) {
        int s = t & 1;
        if (t + 1 < T) {
            LOAD_STAGE(t + 1, s ^ 1);
            asm volatile("cp.async.wait_group 1;" ::: "memory");
        } else {
            asm volatile("cp.async.wait_group 0;" ::: "memory");
        }
        __syncthreads();

        uint32_t stg = smb + s * GSTAGE;
#pragma unroll
        for (int k16 = 0; k16 < 2; k16++) {
            uint32_t aA = stg + aoff + k16 * 32;           // 16 elems * 2B
            uint32_t bA = stg + 2 * BUFB + boff + k16 * 32;
            uint32_t ah[4][4], al[4][4], bh[4][2], bl[4][2];
#pragma unroll
            for (int mf = 0; mf < 4; mf++) {
                uint32_t ad = aA + mf * 16 * ROWB;
                ldm_x4(ah[mf][0], ah[mf][1], ah[mf][2], ah[mf][3], ad);
                ldm_x4(al[mf][0], al[mf][1], al[mf][2], al[mf][3], ad + BUFB);
            }
#pragma unroll
            for (int nf = 0; nf < 4; nf++) {
                uint32_t bd = bA + nf * 8 * ROWB;
                ldm_x2(bh[nf][0], bh[nf][1], bd);
                ldm_x2(bl[nf][0], bl[nf][1], bd + BUFB);
            }
#pragma unroll
            for (int mf = 0; mf < 4; mf++)
#pragma unroll
                for (int nf = 0; nf < 4; nf++) {
                    mma16816(acc[mf][nf], ah[mf], bh[nf]);
                    mma16816(acc[mf][nf], ah[mf], bl[nf]);
                    mma16816(acc[mf][nf], al[mf], bh[nf]);
                }
        }
        __syncthreads();
    }

    // epilogue
    int tr = lane >> 2;
    int tc = (lane & 3) << 1;
#pragma unroll
    for (int mf = 0; mf < 4; mf++) {
        int m = row0 + warp_m * 64 + mf * 16 + tr;
#pragma unroll
        for (int nf = 0; nf < 4; nf++) {
            int n = col0 + warp_n * 32 + nf * 8 + tc;
            *(float2*)(C + (size_t)m * Ntot + n) = make_float2(acc[mf][nf][0], acc[mf][nf][1]);
            *(float2*)(C + (size_t)(m + 8) * Ntot + n) = make_float2(acc[mf][nf][2], acc[mf][nf][3]);
        }
    }
#undef LOAD_STAGE
}

// ---------------- fused RMSNorm + RoPE (per (token, head) row of 128) ----------
__global__ void normrope_kernel(float* __restrict__ x, const float* __restrict__ scale, int heads) {
    int warp = (blockIdx.x * blockDim.x + threadIdx.x) >> 5;
    int lane = threadIdx.x & 31;
    int token = warp / heads;
    int head = warp % heads;
    float* p = x + (size_t)token * heads * KKD + head * KKD;

    float4 v = *(float4*)(p + lane * 4);
    float ss = v.x * v.x + v.y * v.y + v.z * v.z + v.w * v.w;
#pragma unroll
    for (int o = 16; o > 0; o >>= 1) ss += __shfl_xor_sync(0xffffffffu, ss, o);
    float inv = rsqrtf(ss * (1.0f / 128.0f) + 1e-6f);
    float4 sc = *(const float4*)(scale + lane * 4);
    float vv[4];
    vv[0] = v.x * inv * sc.x; vv[1] = v.y * inv * sc.y;
    vv[2] = v.z * inv * sc.z; vv[3] = v.w * inv * sc.w;

    float pf = (float)g_pos[token];
    float out[4];
#pragma unroll
    for (int c = 0; c < 4; c++) {
        int k = lane * 4 + c;
        int j = k & 63;
        float invf = expf(-9.210340371976184f * ((float)j * (1.0f / 64.0f)));
        float sn, cs;
        sincosf(pf * invf, &sn, &cs);
        float partner = __shfl_xor_sync(0xffffffffu, vv[c], 16);
        out[c] = (k < 64) ? (vv[c] * cs - partner * sn) : (vv[c] * cs + partner * sn);
    }
    *(float4*)(p + lane * 4) = make_float4(out[0], out[1], out[2], out[3]);
}

// ---------------- flash attention with segment-causal mask ---------------------
#define KV_STRIDE 129
#define P_STRIDE 65
#define ATT_SMEM_BYTES ((64*128 + 64*KV_STRIDE + 64*P_STRIDE) * 4 + 64 * 4)

__global__ __launch_bounds__(256) void attn_kernel() {
    extern __shared__ float sm[];
    float* Qs = sm;                         // 64 x 128
    float* KVs = Qs + 64 * 128;             // 64 x 129
    float* Ps = KVs + 64 * KV_STRIDE;       // 64 x 65
    int* Sst = (int*)(Ps + 64 * P_STRIDE);  // 64

    const int tid = threadIdx.x;
    const int tx = tid & 15, ty = tid >> 4;
    const int b = blockIdx.z, h = blockIdx.y;
    const int t0 = blockIdx.x * 64;
    const int g = h >> 2;
    const float scale = 0.08838834764831845f;
    const float NEG = -1e30f;

#pragma unroll
    for (int i = 0; i < 8; i++) {
        int r = tid >> 2;
        int c4 = (tid & 3) + i * 4;
        *(float4*)(Qs + r * 128 + c4 * 4) =
            *(const float4*)(g_q + (size_t)(b * TT + t0 + r) * QW + h * KKD + c4 * 4);
    }
    if (tid < 64) {
        int t = t0 + tid;
        Sst[tid] = t - g_pos[b * TT + t];
    }
    __syncthreads();

    const int s_begin = Sst[0] & ~63;
    int my_start[4];
#pragma unroll
    for (int ii = 0; ii < 4; ii++) my_start[ii] = Sst[ty * 4 + ii];

    float m[4], l[4], O[4][8];
#pragma unroll
    for (int ii = 0; ii < 4; ii++) {
        m[ii] = NEG; l[ii] = 0.f;
#pragma unroll
        for (int jj = 0; jj < 8; jj++) O[ii][jj] = 0.f;
    }

    for (int s0 = s_begin; s0 <= t0; s0 += 64) {
#pragma unroll
        for (int i = 0; i < 8; i++) {
            int r = tid >> 2;
            int c4 = (tid & 3) + i * 4;
            float4 vv = *(const float4*)(g_k + (size_t)(b * TT + s0 + r) * KVW + g * KKD + c4 * 4);
            float* dst = KVs + r * KV_STRIDE + c4 * 4;
            dst[0] = vv.x; dst[1] = vv.y; dst[2] = vv.z; dst[3] = vv.w;
        }
        __syncthreads();

        float acc[4][4];
#pragma unroll
        for (int ii = 0; ii < 4; ii++)
#pragma unroll
            for (int jj = 0; jj < 4; jj++) acc[ii][jj] = 0.f;
#pragma unroll 4
        for (int k = 0; k < 128; k++) {
            float qv[4], kv[4];
#pragma unroll
            for (int ii = 0; ii < 4; ii++) qv[ii] = Qs[(ty * 4 + ii) * 128 + k];
#pragma unroll
            for (int jj = 0; jj < 4; jj++) kv[jj] = KVs[(tx + jj * 16) * KV_STRIDE + k];
#pragma unroll
            for (int ii = 0; ii < 4; ii++)
#pragma unroll
                for (int jj = 0; jj < 4; jj++) acc[ii][jj] += qv[ii] * kv[jj];
        }

#pragma unroll
        for (int ii = 0; ii < 4; ii++) {
            int t = t0 + ty * 4 + ii;
            float rmax = NEG;
#pragma unroll
            for (int jj = 0; jj < 4; jj++) {
                int s = s0 + tx + jj * 16;
                bool valid = (s <= t) && (s >= my_start[ii]);
                float val = valid ? acc[ii][jj] * scale : NEG;
                acc[ii][jj] = val;
                rmax = fmaxf(rmax, val);
            }
#pragma unroll
            for (int o = 1; o < 16; o <<= 1)
                rmax = fmaxf(rmax, __shfl_xor_sync(0xffffffffu, rmax, o));
            float mn = fmaxf(m[ii], rmax);
            float corr = __expf(m[ii] - mn);
            m[ii] = mn;
            l[ii] *= corr;
#pragma unroll
            for (int jj = 0; jj < 8; jj++) O[ii][jj] *= corr;
            float rsum = 0.f;
#pragma unroll
            for (int jj = 0; jj < 4; jj++) {
                int s = s0 + tx + jj * 16;
                bool valid = (s <= t) && (s >= my_start[ii]);
                float pv = valid ? __expf(acc[ii][jj] - mn) : 0.f;
                rsum += pv;
                Ps[(ty * 4 + ii) * P_STRIDE + tx + jj * 16] = pv;
            }
#pragma unroll
            for (int o = 1; o < 16; o <<= 1)
                rsum += __shfl_xor_sync(0xffffffffu, rsum, o);
            l[ii] += rsum;
        }
        __syncthreads();

#pragma unroll
        for (int i = 0; i < 8; i++) {
            int r = tid >> 2;
            int c4 = (tid & 3) + i * 4;
            float4 vv = *(const float4*)(g_v + (size_t)(b * TT + s0 + r) * KVW + g * KKD + c4 * 4);
            float* dst = KVs + r * KV_STRIDE + c4 * 4;
            dst[0] = vv.x; dst[1] = vv.y; dst[2] = vv.z; dst[3] = vv.w;
        }
        __syncthreads();

#pragma unroll 2
        for (int s = 0; s < 64; s++) {
            float pr[4], vr[8];
#pragma unroll
            for (int ii = 0; ii < 4; ii++) pr[ii] = Ps[(ty * 4 + ii) * P_STRIDE + s];
#pragma unroll
            for (int jj = 0; jj < 8; jj++) vr[jj] = KVs[s * KV_STRIDE + tx + jj * 16];
#pragma unroll
            for (int ii = 0; ii < 4; ii++)
#pragma unroll
                for (int jj = 0; jj < 8; jj++) O[ii][jj] += pr[ii] * vr[jj];
        }
        __syncthreads();
    }

#pragma unroll
    for (int ii = 0; ii < 4; ii++) {
        float invl = 1.0f / l[ii];
        float* dst = g_attn + (size_t)(b * TT + t0 + ty * 4 + ii) * QW + h * KKD;
#pragma unroll
        for (int jj = 0; jj < 8; jj++) dst[tx + jj * 16] = O[ii][jj] * invl;
    }
}

// ---------------- launch ----------------
extern "C" void kernel_launch(void* const* d_in, const int* in_sizes, int n_in,
                              void* d_out, int out_size) {
    const float* hidden  = (const float*)d_in[0];
    const float* wq      = (const float*)d_in[1];
    const float* wk      = (const float*)d_in[2];
    const float* wv      = (const float*)d_in[3];
    const float* wo      = (const float*)d_in[4];
    const float* q_scale = (const float*)d_in[5];
    const float* k_scale = (const float*)d_in[6];
    const int*   seg     = (const int*)d_in[7];
    float* out = (float*)d_out;

    float *q, *k, *v, *attn;
    __nv_bfloat16 *hidh, *hidl, *atth, *attl;
    __nv_bfloat16 *wqh, *wql, *wkh, *wkl, *wvh, *wvl, *woh, *wol;
    cudaGetSymbolAddress((void**)&q, g_q);
    cudaGetSymbolAddress((void**)&k, g_k);
    cudaGetSymbolAddress((void**)&v, g_v);
    cudaGetSymbolAddress((void**)&attn, g_attn);
    cudaGetSymbolAddress((void**)&hidh, g_hid_hi);
    cudaGetSymbolAddress((void**)&hidl, g_hid_lo);
    cudaGetSymbolAddress((void**)&atth, g_att_hi);
    cudaGetSymbolAddress((void**)&attl, g_att_lo);
    cudaGetSymbolAddress((void**)&wqh, g_wq_hi);
    cudaGetSymbolAddress((void**)&wql, g_wq_lo);
    cudaGetSymbolAddress((void**)&wkh, g_wk_hi);
    cudaGetSymbolAddress((void**)&wkl, g_wk_lo);
    cudaGetSymbolAddress((void**)&wvh, g_wv_hi);
    cudaGetSymbolAddress((void**)&wvl, g_wv_lo);
    cudaGetSymbolAddress((void**)&woh, g_wo_hi);
    cudaGetSymbolAddress((void**)&wol, g_wo_lo);

    cudaFuncSetAttribute(attn_kernel, cudaFuncAttributeMaxDynamicSharedMemorySize,
                         ATT_SMEM_BYTES);
    cudaFuncSetAttribute(mma_gemm_kernel, cudaFuncAttributeMaxDynamicSharedMemorySize,
                         GSM);

    pos_kernel<<<NTOK / 256, 256>>>(seg);

    // operand prep
    {
        int n4 = NTOK * DD / 4;
        split_kernel<<<(n4 + 255) / 256, 256>>>(hidden, hidh, hidl, n4);
    }
    tsplit_kernel<<<dim3(QW / 32, DD / 32), dim3(32, 8)>>>(wq, wqh, wql, DD, QW);
    tsplit_kernel<<<dim3(KVW / 32, DD / 32), dim3(32, 8)>>>(wk, wkh, wkl, DD, KVW);
    tsplit_kernel<<<dim3(KVW / 32, DD / 32), dim3(32, 8)>>>(wv, wvh, wvl, DD, KVW);
    tsplit_kernel<<<dim3(DD / 32, QW / 32), dim3(32, 8)>>>(wo, woh, wol, QW, DD);

    // projections (3xBF16 mma.sync)
    mma_gemm_kernel<<<dim3(QW / 128, NTOK / 128), 256, GSM>>>(
        hidh, hidl, wqh, wql, q, QW, DD);
    mma_gemm_kernel<<<dim3(KVW / 128, NTOK / 128), 256, GSM>>>(
        hidh, hidl, wkh, wkl, k, KVW, DD);
    mma_gemm_kernel<<<dim3(KVW / 128, NTOK / 128), 256, GSM>>>(
        hidh, hidl, wvh, wvl, v, KVW, DD);

    normrope_kernel<<<(NTOK * HH) / 8, 256>>>(q, q_scale, HH);
    normrope_kernel<<<(NTOK * GG) / 8, 256>>>(k, k_scale, GG);

    attn_kernel<<<dim3(TT / 64, HH, BB), 256, ATT_SMEM_BYTES>>>();

    {
        int n4 = NTOK * QW / 4;
        split_kernel<<<(n4 + 255) / 256, 256>>>(attn, atth, attl, n4);
    }
    mma_gemm_kernel<<<dim3(DD / 128, NTOK / 128), 256, GSM>>>(
        atth, attl, woh, wol, out, DD, QW);
}

// round 5
// speedup vs baseline: 2.1615x; 1.1642x over previous
#include <cuda_runtime.h>
#include <cuda_bf16.h>
#include <math.h>
#include <stdint.h>

#define BB 4
#define TT 2048
#define DD 2048
#define HH 16
#define GG 4
#define KKD 128
#define NTOK (BB*TT)          /* 8192 */
#define QW (HH*KKD)           /* 2048 */
#define KVW (GG*KKD)          /* 512  */

// ---------------- scratch (static device globals; no allocation) ----------------
__device__ float g_q[(size_t)NTOK*QW];
__device__ float g_k[(size_t)NTOK*KVW];
__device__ float g_v[(size_t)NTOK*KVW];
__device__ int   g_pos[NTOK];

__device__ __nv_bfloat16 g_qhi[(size_t)NTOK*QW];
__device__ __nv_bfloat16 g_qlo[(size_t)NTOK*QW];
__device__ __nv_bfloat16 g_khi[(size_t)NTOK*KVW];
__device__ __nv_bfloat16 g_klo[(size_t)NTOK*KVW];
__device__ __nv_bfloat16 g_vhi[(size_t)NTOK*KVW];
__device__ __nv_bfloat16 g_vlo[(size_t)NTOK*KVW];

__device__ __nv_bfloat16 g_hid_hi[(size_t)NTOK*DD];
__device__ __nv_bfloat16 g_hid_lo[(size_t)NTOK*DD];
__device__ __nv_bfloat16 g_att_hi[(size_t)NTOK*QW];
__device__ __nv_bfloat16 g_att_lo[(size_t)NTOK*QW];
__device__ __nv_bfloat16 g_wq_hi[(size_t)QW*DD];
__device__ __nv_bfloat16 g_wq_lo[(size_t)QW*DD];
__device__ __nv_bfloat16 g_wk_hi[(size_t)KVW*DD];
__device__ __nv_bfloat16 g_wk_lo[(size_t)KVW*DD];
__device__ __nv_bfloat16 g_wv_hi[(size_t)KVW*DD];
__device__ __nv_bfloat16 g_wv_lo[(size_t)KVW*DD];
__device__ __nv_bfloat16 g_wo_hi[(size_t)DD*QW];
__device__ __nv_bfloat16 g_wo_lo[(size_t)DD*QW];

// ---------------- base-ISA PTX helpers ----------------
__device__ __forceinline__ uint32_t smem_u32(const void* p) {
    uint32_t a;
    asm("{ .reg .u64 t; cvta.to.shared.u64 t, %1; cvt.u32.u64 %0, t; }" : "=r"(a) : "l"(p));
    return a;
}
__device__ __forceinline__ void cp16(uint32_t saddr, const void* g) {
    asm volatile("cp.async.cg.shared.global [%0], [%1], 16;" :: "r"(saddr), "l"(g) : "memory");
}
__device__ __forceinline__ void ldm_x4(uint32_t& r0, uint32_t& r1, uint32_t& r2, uint32_t& r3, uint32_t a) {
    asm volatile("ldmatrix.sync.aligned.m8n8.x4.shared.b16 {%0,%1,%2,%3}, [%4];"
                 : "=r"(r0), "=r"(r1), "=r"(r2), "=r"(r3) : "r"(a));
}
__device__ __forceinline__ void ldm_x4t(uint32_t& r0, uint32_t& r1, uint32_t& r2, uint32_t& r3, uint32_t a) {
    asm volatile("ldmatrix.sync.aligned.m8n8.x4.trans.shared.b16 {%0,%1,%2,%3}, [%4];"
                 : "=r"(r0), "=r"(r1), "=r"(r2), "=r"(r3) : "r"(a));
}
__device__ __forceinline__ void ldm_x2(uint32_t& r0, uint32_t& r1, uint32_t a) {
    asm volatile("ldmatrix.sync.aligned.m8n8.x2.shared.b16 {%0,%1}, [%2];"
                 : "=r"(r0), "=r"(r1) : "r"(a));
}
__device__ __forceinline__ void mma16816(float* d, const uint32_t* a, const uint32_t* b) {
    asm volatile(
        "mma.sync.aligned.m16n8k16.row.col.f32.bf16.bf16.f32 "
        "{%0,%1,%2,%3}, {%4,%5,%6,%7}, {%8,%9}, {%0,%1,%2,%3};"
        : "+f"(d[0]), "+f"(d[1]), "+f"(d[2]), "+f"(d[3])
        : "r"(a[0]), "r"(a[1]), "r"(a[2]), "r"(a[3]), "r"(b[0]), "r"(b[1]));
}
__device__ __forceinline__ uint32_t pkhl(float x, float y) {
    __nv_bfloat162 t = __floats2bfloat162_rn(x, y);
    return *reinterpret_cast<uint32_t*>(&t);
}
__device__ __forceinline__ float bfres(float x) {
    return x - __bfloat162float(__float2bfloat16(x));
}

// ---------------- positions from sorted segment ids ----------------
__global__ void pos_kernel(const int* __restrict__ seg) {
    int idx = blockIdx.x * blockDim.x + threadIdx.x;
    if (idx >= NTOK) return;
    int b = idx / TT, t = idx % TT;
    const int* s = seg + b * TT;
    int v = s[t];
    int lo = 0, hi = t;
    while (lo < hi) { int mid = (lo + hi) >> 1; if (s[mid] < v) lo = mid + 1; else hi = mid; }
    g_pos[idx] = t - lo;
}

// ---------------- elementwise fp32 -> (hi, lo) bf16 split ----------------
__global__ void split_kernel(const float* __restrict__ x,
                             __nv_bfloat16* __restrict__ hi,
                             __nv_bfloat16* __restrict__ lo, int n4) {
    int i = blockIdx.x * blockDim.x + threadIdx.x;
    if (i >= n4) return;
    float4 v = ((const float4*)x)[i];
    __nv_bfloat16 h0 = __float2bfloat16(v.x);
    __nv_bfloat16 h1 = __float2bfloat16(v.y);
    __nv_bfloat16 h2 = __float2bfloat16(v.z);
    __nv_bfloat16 h3 = __float2bfloat16(v.w);
    __nv_bfloat162 ha, hb, la, lb;
    ha.x = h0; ha.y = h1; hb.x = h2; hb.y = h3;
    la.x = __float2bfloat16(v.x - __bfloat162float(h0));
    la.y = __float2bfloat16(v.y - __bfloat162float(h1));
    lb.x = __float2bfloat16(v.z - __bfloat162float(h2));
    lb.y = __float2bfloat16(v.w - __bfloat162float(h3));
    ((__nv_bfloat162*)hi)[2*i] = ha; ((__nv_bfloat162*)hi)[2*i+1] = hb;
    ((__nv_bfloat162*)lo)[2*i] = la; ((__nv_bfloat162*)lo)[2*i+1] = lb;
}

// ---------------- weight transpose + split: W[Rk,N] -> T[N,Rk] hi/lo bf16 -----
__global__ void tsplit_kernel(const float* __restrict__ W,
                              __nv_bfloat16* __restrict__ hi,
                              __nv_bfloat16* __restrict__ lo, int Rk, int N) {
    __shared__ float tile[32][33];
    int tx = threadIdx.x;
    int x = blockIdx.x * 32 + tx;
    int y0 = blockIdx.y * 32;
    for (int i = threadIdx.y; i < 32; i += 8)
        tile[i][tx] = W[(size_t)(y0 + i) * N + x];
    __syncthreads();
    int k = y0 + tx;
    for (int i = threadIdx.y; i < 32; i += 8) {
        int n = blockIdx.x * 32 + i;
        float val = tile[tx][i];
        __nv_bfloat16 h = __float2bfloat16(val);
        hi[(size_t)n * Rk + k] = h;
        lo[(size_t)n * Rk + k] = __float2bfloat16(val - __bfloat162float(h));
    }
}

// ---------------- 3xBF16 GEMM via mma.sync, 4-stage cp.async pipeline ---------
#define ROWB 80
#define BUFB 10240
#define GSTAGE (4*BUFB)
#define GSM (4*GSTAGE)          /* 163840 B */

__global__ __launch_bounds__(256, 1) void mma_gemm_kernel(
    const __nv_bfloat16* __restrict__ Ahi, const __nv_bfloat16* __restrict__ Alo,
    const __nv_bfloat16* __restrict__ Bhi, const __nv_bfloat16* __restrict__ Blo,
    float* __restrict__ C, int Ntot, int Kd)
{
    extern __shared__ __align__(128) char smbuf[];
    const int tid = threadIdx.x;
    const int wid = tid >> 5, lane = tid & 31;
    const int warp_m = wid >> 2, warp_n = wid & 3;
    const int row0 = blockIdx.y * 128, col0 = blockIdx.x * 128;
    const uint32_t smb = smem_u32(smbuf);

    const __nv_bfloat16* bases[4] = {
        Ahi + (size_t)row0 * Kd, Alo + (size_t)row0 * Kd,
        Bhi + (size_t)col0 * Kd, Blo + (size_t)col0 * Kd };

    float acc[4][4][4];
#pragma unroll
    for (int i = 0; i < 4; i++)
#pragma unroll
        for (int j = 0; j < 4; j++)
#pragma unroll
            for (int c = 0; c < 4; c++) acc[i][j][c] = 0.f;

    const int T = Kd >> 5;

    int ld_buf[8], ld_row[8], ld_c[8];
#pragma unroll
    for (int i = 0; i < 8; i++) {
        int id = tid + (i << 8);
        ld_buf[i] = id >> 9;
        int rem = id & 511;
        ld_row[i] = rem >> 2;
        ld_c[i] = rem & 3;
    }

#define LOAD_STAGE(t, s) do {                                                   \
    int k0_ = (t) << 5;                                                         \
    _Pragma("unroll")                                                           \
    for (int i_ = 0; i_ < 8; i_++) {                                            \
        uint32_t sa = smb + (s) * GSTAGE + ld_buf[i_] * BUFB +                  \
                      ld_row[i_] * ROWB + ld_c[i_] * 16;                        \
        const __nv_bfloat16* g = bases[ld_buf[i_]] +                            \
            (size_t)ld_row[i_] * Kd + k0_ + ld_c[i_] * 8;                       \
        cp16(sa, g);                                                            \
    }                                                                           \
    asm volatile("cp.async.commit_group;" ::: "memory");                        \
} while (0)

    const uint32_t aoff = (uint32_t)((warp_m * 64 + (lane & 15)) * ROWB + ((lane >> 4) << 3) * 2);
    const uint32_t boff = (uint32_t)((warp_n * 32 + (lane & 7)) * ROWB + (((lane >> 3) & 1) << 3) * 2);

    LOAD_STAGE(0, 0);
    LOAD_STAGE(1, 1);
    LOAD_STAGE(2, 2);

    for (int t = 0; t < T; t++) {
        int s = t & 3;
        if (t <= T - 3)      asm volatile("cp.async.wait_group 2;" ::: "memory");
        else if (t == T - 2) asm volatile("cp.async.wait_group 1;" ::: "memory");
        else                 asm volatile("cp.async.wait_group 0;" ::: "memory");
        __syncthreads();
        if (t + 3 < T) LOAD_STAGE(t + 3, (t + 3) & 3);

        uint32_t stg = smb + s * GSTAGE;
#pragma unroll
        for (int k16 = 0; k16 < 2; k16++) {
            uint32_t aA = stg + aoff + k16 * 32;
            uint32_t bA = stg + 2 * BUFB + boff + k16 * 32;
            uint32_t ah[4][4], al[4][4], bh[4][2], bl[4][2];
#pragma unroll
            for (int mf = 0; mf < 4; mf++) {
                uint32_t ad = aA + mf * 16 * ROWB;
                ldm_x4(ah[mf][0], ah[mf][1], ah[mf][2], ah[mf][3], ad);
                ldm_x4(al[mf][0], al[mf][1], al[mf][2], al[mf][3], ad + BUFB);
            }
#pragma unroll
            for (int nf = 0; nf < 4; nf++) {
                uint32_t bd = bA + nf * 8 * ROWB;
                ldm_x2(bh[nf][0], bh[nf][1], bd);
                ldm_x2(bl[nf][0], bl[nf][1], bd + BUFB);
            }
#pragma unroll
            for (int mf = 0; mf < 4; mf++)
#pragma unroll
                for (int nf = 0; nf < 4; nf++) {
                    mma16816(acc[mf][nf], ah[mf], bh[nf]);
                    mma16816(acc[mf][nf], ah[mf], bl[nf]);
                    mma16816(acc[mf][nf], al[mf], bh[nf]);
                }
        }
    }

    int tr = lane >> 2;
    int tc = (lane & 3) << 1;
#pragma unroll
    for (int mf = 0; mf < 4; mf++) {
        int m = row0 + warp_m * 64 + mf * 16 + tr;
#pragma unroll
        for (int nf = 0; nf < 4; nf++) {
            int n = col0 + warp_n * 32 + nf * 8 + tc;
            *(float2*)(C + (size_t)m * Ntot + n) = make_float2(acc[mf][nf][0], acc[mf][nf][1]);
            *(float2*)(C + (size_t)(m + 8) * Ntot + n) = make_float2(acc[mf][nf][2], acc[mf][nf][3]);
        }
    }
#undef LOAD_STAGE
}

// ------- fused RMSNorm + RoPE, writes bf16 hi/lo -------
__global__ void normrope_kernel(const float* __restrict__ x, const float* __restrict__ scale,
                                __nv_bfloat16* __restrict__ hi, __nv_bfloat16* __restrict__ lo,
                                int heads) {
    int warp = (blockIdx.x * blockDim.x + threadIdx.x) >> 5;
    int lane = threadIdx.x & 31;
    int token = warp / heads;
    int head = warp % heads;
    const float* p = x + (size_t)token * heads * KKD + head * KKD;

    float4 v = *(const float4*)(p + lane * 4);
    float ss = v.x * v.x + v.y * v.y + v.z * v.z + v.w * v.w;
#pragma unroll
    for (int o = 16; o > 0; o >>= 1) ss += __shfl_xor_sync(0xffffffffu, ss, o);
    float inv = rsqrtf(ss * (1.0f / 128.0f) + 1e-6f);
    float4 sc = *(const float4*)(scale + lane * 4);
    float vv[4];
    vv[0] = v.x * inv * sc.x; vv[1] = v.y * inv * sc.y;
    vv[2] = v.z * inv * sc.z; vv[3] = v.w * inv * sc.w;

    float pf = (float)g_pos[token];
    float out[4];
#pragma unroll
    for (int c = 0; c < 4; c++) {
        int k = lane * 4 + c;
        int j = k & 63;
        float invf = expf(-9.210340371976184f * ((float)j * (1.0f / 64.0f)));
        float sn, cs;
        sincosf(pf * invf, &sn, &cs);
        float partner = __shfl_xor_sync(0xffffffffu, vv[c], 16);
        out[c] = (k < 64) ? (vv[c] * cs - partner * sn) : (vv[c] * cs + partner * sn);
    }
    size_t base = (size_t)token * heads * KKD + head * KKD + lane * 4;
    __nv_bfloat162 h01, h23, l01, l23;
    h01.x = __float2bfloat16(out[0]); h01.y = __float2bfloat16(out[1]);
    h23.x = __float2bfloat16(out[2]); h23.y = __float2bfloat16(out[3]);
    l01.x = __float2bfloat16(out[0] - __bfloat162float(h01.x));
    l01.y = __float2bfloat16(out[1] - __bfloat162float(h01.y));
    l23.x = __float2bfloat16(out[2] - __bfloat162float(h23.x));
    l23.y = __float2bfloat16(out[3] - __bfloat162float(h23.y));
    *(__nv_bfloat162*)(hi + base) = h01; *(__nv_bfloat162*)(hi + base + 2) = h23;
    *(__nv_bfloat162*)(lo + base) = l01; *(__nv_bfloat162*)(lo + base + 2) = l23;
}

// ---------------- tensor-core flash attention, segment-causal -----------------
// BM=BN=64, D=128, 128 threads (4 warps, each 16 rows).
#define KVSTR 136                      /* bf16 elems per smem row */
#define ABUF (64*KVSTR*2)              /* 17408 B per buffer */
#define ATT_SMEM (4*ABUF + 256)        /* Qhi Qlo KVhi KVlo + Sst */

__global__ __launch_bounds__(128) void attn_mma_kernel() {
    extern __shared__ __align__(128) char smraw[];
    char* sQhi = smraw;
    char* sQlo = smraw + ABUF;
    char* sKVhi = smraw + 2 * ABUF;
    char* sKVlo = smraw + 3 * ABUF;
    int* Sst = (int*)(smraw + 4 * ABUF);
    const uint32_t uQhi = smem_u32(sQhi);
    const uint32_t uKVhi = smem_u32(sKVhi);

    const int tid = threadIdx.x;
    const int warp = tid >> 5, lane = tid & 31;
    const int b = blockIdx.z, h = blockIdx.y;
    const int t0 = blockIdx.x * 64;
    const int g = h >> 2;
    const float scale = 0.08838834764831845f;
    const float NEG = -1e30f;

    // load Q tile (hi/lo): 2 threads per row, 64 bf16 each
    {
        int r = tid >> 1, half = tid & 1;
        size_t gofs = (size_t)(b * TT + t0 + r) * QW + h * KKD + half * 64;
        const uint4* sh = (const uint4*)(g_qhi + gofs);
        const uint4* sl = (const uint4*)(g_qlo + gofs);
        uint4* dh = (uint4*)(sQhi + (r * KVSTR + half * 64) * 2);
        uint4* dl = (uint4*)(sQlo + (r * KVSTR + half * 64) * 2);
#pragma unroll
        for (int i = 0; i < 8; i++) { dh[i] = sh[i]; dl[i] = sl[i]; }
    }
    if (tid < 64) {
        int t = t0 + tid;
        Sst[tid] = t - g_pos[b * TT + t];
    }
    __syncthreads();

    const int s_begin = Sst[0] & ~63;
    const int r_lo = warp * 16 + (lane >> 2);
    const int t_0 = t0 + r_lo, t_1 = t_0 + 8;
    const int st0 = Sst[r_lo], st1 = Sst[r_lo + 8];
    const int qk = (lane & 3) << 1;

    float m0 = NEG, m1 = NEG, l0 = 0.f, l1 = 0.f;
    float o[16][4];
#pragma unroll
    for (int i = 0; i < 16; i++)
#pragma unroll
        for (int c = 0; c < 4; c++) o[i][c] = 0.f;

    for (int s0 = s_begin; s0 <= t0; s0 += 64) {
        // ---- load K tile hi/lo ----
        {
            int r = tid >> 1, half = tid & 1;
            size_t gofs = (size_t)(b * TT + s0 + r) * KVW + g * KKD + half * 64;
            const uint4* sh = (const uint4*)(g_khi + gofs);
            const uint4* sl = (const uint4*)(g_klo + gofs);
            uint4* dh = (uint4*)(sKVhi + (r * KVSTR + half * 64) * 2);
            uint4* dl = (uint4*)(sKVlo + (r * KVSTR + half * 64) * 2);
#pragma unroll
            for (int i = 0; i < 8; i++) { dh[i] = sh[i]; dl[i] = sl[i]; }
        }
        __syncthreads();

        // ---- S = Q K^T (3xBF16) ----
        float sfr[8][4];
#pragma unroll
        for (int i = 0; i < 8; i++)
#pragma unroll
            for (int c = 0; c < 4; c++) sfr[i][c] = 0.f;

#pragma unroll
        for (int k16 = 0; k16 < 8; k16++) {
            uint32_t qa = uQhi + ((warp * 16 + (lane & 15)) * KVSTR + k16 * 16 + ((lane >> 4) << 3)) * 2;
            uint32_t ah[4], al[4];
            ldm_x4(ah[0], ah[1], ah[2], ah[3], qa);
            ldm_x4(al[0], al[1], al[2], al[3], qa + ABUF);
#pragma unroll
            for (int f = 0; f < 4; f++) {
                uint32_t ka = uKVhi + ((f * 16 + (lane & 7) + ((lane >> 4) << 3)) * KVSTR
                                       + k16 * 16 + (((lane >> 3) & 1) << 3)) * 2;
                uint32_t bh[4], bl[4];
                ldm_x4(bh[0], bh[1], bh[2], bh[3], ka);
                ldm_x4(bl[0], bl[1], bl[2], bl[3], ka + ABUF);
                mma16816(sfr[2*f],   ah, bh);
                mma16816(sfr[2*f],   ah, bl);
                mma16816(sfr[2*f],   al, bh);
                mma16816(sfr[2*f+1], ah, bh + 2);
                mma16816(sfr[2*f+1], ah, bl + 2);
                mma16816(sfr[2*f+1], al, bh + 2);
            }
        }

        // ---- mask + online softmax (rows t_0, t_1 per thread) ----
        float rmax0 = NEG, rmax1 = NEG;
#pragma unroll
        for (int nf = 0; nf < 8; nf++) {
            int c0 = s0 + nf * 8 + qk, c1 = c0 + 1;
            sfr[nf][0] = (c0 <= t_0 && c0 >= st0) ? sfr[nf][0] * scale : NEG;
            sfr[nf][1] = (c1 <= t_0 && c1 >= st0) ? sfr[nf][1] * scale : NEG;
            sfr[nf][2] = (c0 <= t_1 && c0 >= st1) ? sfr[nf][2] * scale : NEG;
            sfr[nf][3] = (c1 <= t_1 && c1 >= st1) ? sfr[nf][3] * scale : NEG;
            rmax0 = fmaxf(rmax0, fmaxf(sfr[nf][0], sfr[nf][1]));
            rmax1 = fmaxf(rmax1, fmaxf(sfr[nf][2], sfr[nf][3]));
        }
        rmax0 = fmaxf(rmax0, __shfl_xor_sync(0xffffffffu, rmax0, 1));
        rmax0 = fmaxf(rmax0, __shfl_xor_sync(0xffffffffu, rmax0, 2));
        rmax1 = fmaxf(rmax1, __shfl_xor_sync(0xffffffffu, rmax1, 1));
        rmax1 = fmaxf(rmax1, __shfl_xor_sync(0xffffffffu, rmax1, 2));

        float mn0 = fmaxf(m0, rmax0), mn1 = fmaxf(m1, rmax1);
        float corr0 = __expf(m0 - mn0), corr1 = __expf(m1 - mn1);
        m0 = mn0; m1 = mn1;
        l0 *= corr0; l1 *= corr1;
#pragma unroll
        for (int i = 0; i < 16; i++) {
            o[i][0] *= corr0; o[i][1] *= corr0;
            o[i][2] *= corr1; o[i][3] *= corr1;
        }
        float sum0 = 0.f, sum1 = 0.f;
#pragma unroll
        for (int nf = 0; nf < 8; nf++) {
            float p0 = (sfr[nf][0] > -5e29f) ? __expf(sfr[nf][0] - mn0) : 0.f;
            float p1 = (sfr[nf][1] > -5e29f) ? __expf(sfr[nf][1] - mn0) : 0.f;
            float p2 = (sfr[nf][2] > -5e29f) ? __expf(sfr[nf][2] - mn1) : 0.f;
            float p3 = (sfr[nf][3] > -5e29f) ? __expf(sfr[nf][3] - mn1) : 0.f;
            sfr[nf][0] = p0; sfr[nf][1] = p1; sfr[nf][2] = p2; sfr[nf][3] = p3;
            sum0 += p0 + p1; sum1 += p2 + p3;
        }
        sum0 += __shfl_xor_sync(0xffffffffu, sum0, 1);
        sum0 += __shfl_xor_sync(0xffffffffu, sum0, 2);
        sum1 += __shfl_xor_sync(0xffffffffu, sum1, 1);
        sum1 += __shfl_xor_sync(0xffffffffu, sum1, 2);
        l0 += sum0; l1 += sum1;

        __syncthreads();   // all warps done reading K

        // ---- load V tile hi/lo (overwrite KV buffer) ----
        {
            int r = tid >> 1, half = tid & 1;
            size_t gofs = (size_t)(b * TT + s0 + r) * KVW + g * KKD + half * 64;
            const uint4* sh = (const uint4*)(g_vhi + gofs);
            const uint4* sl = (const uint4*)(g_vlo + gofs);
            uint4* dh = (uint4*)(sKVhi + (r * KVSTR + half * 64) * 2);
            uint4* dl = (uint4*)(sKVlo + (r * KVSTR + half * 64) * 2);
#pragma unroll
            for (int i = 0; i < 8; i++) { dh[i] = sh[i]; dl[i] = sl[i]; }
        }
        __syncthreads();

        // ---- O += P V (3xBF16; P from registers) ----
#pragma unroll
        for (int j = 0; j < 4; j++) {
            uint32_t ph[4], pl[4];
            ph[0] = pkhl(sfr[2*j][0],   sfr[2*j][1]);
            ph[1] = pkhl(sfr[2*j][2],   sfr[2*j][3]);
            ph[2] = pkhl(sfr[2*j+1][0], sfr[2*j+1][1]);
            ph[3] = pkhl(sfr[2*j+1][2], sfr[2*j+1][3]);
            pl[0] = pkhl(bfres(sfr[2*j][0]),   bfres(sfr[2*j][1]));
            pl[1] = pkhl(bfres(sfr[2*j][2]),   bfres(sfr[2*j][3]));
            pl[2] = pkhl(bfres(sfr[2*j+1][0]), bfres(sfr[2*j+1][1]));
            pl[3] = pkhl(bfres(sfr[2*j+1][2]), bfres(sfr[2*j+1][3]));
#pragma unroll
            for (int f = 0; f < 8; f++) {
                uint32_t va = uKVhi + ((j * 16 + (lane & 7) + (((lane >> 3) & 1) << 3)) * KVSTR
                                       + f * 16 + ((lane >> 4) << 3)) * 2;
                uint32_t vh[4], vl[4];
                ldm_x4t(vh[0], vh[1], vh[2], vh[3], va);
                ldm_x4t(vl[0], vl[1], vl[2], vl[3], va + ABUF);
                mma16816(o[2*f],   ph, vh);
                mma16816(o[2*f],   ph, vl);
                mma16816(o[2*f],   pl, vh);
                mma16816(o[2*f+1], ph, vh + 2);
                mma16816(o[2*f+1], ph, vl + 2);
                mma16816(o[2*f+1], pl, vh + 2);
            }
        }
        __syncthreads();   // PV readers done before next K load
    }

    // ---- epilogue: normalize, split to bf16 hi/lo, store ----
    float inv0 = 1.0f / l0, inv1 = 1.0f / l1;
#pragma unroll
    for (int nf = 0; nf < 16; nf++) {
        int c = h * KKD + nf * 8 + qk;
        size_t a0 = (size_t)(b * TT + t_0) * QW + c;
        size_t a1 = (size_t)(b * TT + t_1) * QW + c;
        float v0 = o[nf][0] * inv0, v1 = o[nf][1] * inv0;
        float v2 = o[nf][2] * inv1, v3 = o[nf][3] * inv1;
        __nv_bfloat162 h0, h1, l0v, l1v;
        h0.x = __float2bfloat16(v0); h0.y = __float2bfloat16(v1);
        h1.x = __float2bfloat16(v2); h1.y = __float2bfloat16(v3);
        l0v.x = __float2bfloat16(v0 - __bfloat162float(h0.x));
        l0v.y = __float2bfloat16(v1 - __bfloat162float(h0.y));
        l1v.x = __float2bfloat16(v2 - __bfloat162float(h1.x));
        l1v.y = __float2bfloat16(v3 - __bfloat162float(h1.y));
        *(__nv_bfloat162*)(g_att_hi + a0) = h0;
        *(__nv_bfloat162*)(g_att_lo + a0) = l0v;
        *(__nv_bfloat162*)(g_att_hi + a1) = h1;
        *(__nv_bfloat162*)(g_att_lo + a1) = l1v;
    }
}

// ---------------- launch ----------------
extern "C" void kernel_launch(void* const* d_in, const int* in_sizes, int n_in,
                              void* d_out, int out_size) {
    const float* hidden  = (const float*)d_in[0];
    const float* wq      = (const float*)d_in[1];
    const float* wk      = (const float*)d_in[2];
    const float* wv      = (const float*)d_in[3];
    const float* wo      = (const float*)d_in[4];
    const float* q_scale = (const float*)d_in[5];
    const float* k_scale = (const float*)d_in[6];
    const int*   seg     = (const int*)d_in[7];
    float* out = (float*)d_out;

    float *q, *k, *v;
    __nv_bfloat16 *hidh, *hidl, *atth, *attl;
    __nv_bfloat16 *qhi, *qlo, *khi, *klo, *vhi, *vlo;
    __nv_bfloat16 *wqh, *wql, *wkh, *wkl, *wvh, *wvl, *woh, *wol;
    cudaGetSymbolAddress((void**)&q, g_q);
    cudaGetSymbolAddress((void**)&k, g_k);
    cudaGetSymbolAddress((void**)&v, g_v);
    cudaGetSymbolAddress((void**)&hidh, g_hid_hi);
    cudaGetSymbolAddress((void**)&hidl, g_hid_lo);
    cudaGetSymbolAddress((void**)&atth, g_att_hi);
    cudaGetSymbolAddress((void**)&attl, g_att_lo);
    cudaGetSymbolAddress((void**)&qhi, g_qhi);
    cudaGetSymbolAddress((void**)&qlo, g_qlo);
    cudaGetSymbolAddress((void**)&khi, g_khi);
    cudaGetSymbolAddress((void**)&klo, g_klo);
    cudaGetSymbolAddress((void**)&vhi, g_vhi);
    cudaGetSymbolAddress((void**)&vlo, g_vlo);
    cudaGetSymbolAddress((void**)&wqh, g_wq_hi);
    cudaGetSymbolAddress((void**)&wql, g_wq_lo);
    cudaGetSymbolAddress((void**)&wkh, g_wk_hi);
    cudaGetSymbolAddress((void**)&wkl, g_wk_lo);
    cudaGetSymbolAddress((void**)&wvh, g_wv_hi);
    cudaGetSymbolAddress((void**)&wvl, g_wv_lo);
    cudaGetSymbolAddress((void**)&woh, g_wo_hi);
    cudaGetSymbolAddress((void**)&wol, g_wo_lo);

    cudaFuncSetAttribute(mma_gemm_kernel, cudaFuncAttributeMaxDynamicSharedMemorySize, GSM);
    cudaFuncSetAttribute(attn_mma_kernel, cudaFuncAttributeMaxDynamicSharedMemorySize, ATT_SMEM);

    pos_kernel<<<NTOK / 256, 256>>>(seg);

    {
        int n4 = NTOK * DD / 4;
        split_kernel<<<(n4 + 255) / 256, 256>>>(hidden, hidh, hidl, n4);
    }
    tsplit_kernel<<<dim3(QW / 32, DD / 32), dim3(32, 8)>>>(wq, wqh, wql, DD, QW);
    tsplit_kernel<<<dim3(KVW / 32, DD / 32), dim3(32, 8)>>>(wk, wkh, wkl, DD, KVW);
    tsplit_kernel<<<dim3(KVW / 32, DD / 32), dim3(32, 8)>>>(wv, wvh, wvl, DD, KVW);
    tsplit_kernel<<<dim3(DD / 32, QW / 32), dim3(32, 8)>>>(wo, woh, wol, QW, DD);

    mma_gemm_kernel<<<dim3(QW / 128, NTOK / 128), 256, GSM>>>(
        hidh, hidl, wqh, wql, q, QW, DD);
    mma_gemm_kernel<<<dim3(KVW / 128, NTOK / 128), 256, GSM>>>(
        hidh, hidl, wkh, wkl, k, KVW, DD);
    mma_gemm_kernel<<<dim3(KVW / 128, NTOK / 128), 256, GSM>>>(
        hidh, hidl, wvh, wvl, v, KVW, DD);

    normrope_kernel<<<(NTOK * HH) / 8, 256>>>(q, q_scale, qhi, qlo, HH);
    normrope_kernel<<<(NTOK * GG) / 8, 256>>>(k, k_scale, khi, klo, GG);
    {
        int n4 = NTOK * KVW / 4;
        split_kernel<<<(n4 + 255) / 256, 256>>>(v, vhi, vlo, n4);
    }

    attn_mma_kernel<<<dim3(TT / 64, HH, BB), 128, ATT_SMEM>>>();

    mma_gemm_kernel<<<dim3(DD / 128, NTOK / 128), 256, GSM>>>(
        atth, attl, woh, wol, out, DD, QW);
}

// round 6
// speedup vs baseline: 2.4263x; 1.1225x over previous
#include <cuda_runtime.h>
#include <cuda_bf16.h>
#include <math.h>
#include <stdint.h>

#define BB 4
#define TT 2048
#define DD 2048
#define HH 16
#define GG 4
#define KKD 128
#define NTOK (BB*TT)          /* 8192 */
#define QW (HH*KKD)           /* 2048 */
#define KVW (GG*KKD)          /* 512  */

// ---------------- scratch (static device globals; no allocation) ----------------
__device__ float g_q[(size_t)NTOK*QW];
__device__ float g_k[(size_t)NTOK*KVW];
__device__ float g_v[(size_t)NTOK*KVW];
__device__ int   g_pos[NTOK];

__device__ __nv_bfloat16 g_qhi[(size_t)NTOK*QW];
__device__ __nv_bfloat16 g_qlo[(size_t)NTOK*QW];
__device__ __nv_bfloat16 g_khi[(size_t)NTOK*KVW];
__device__ __nv_bfloat16 g_klo[(size_t)NTOK*KVW];
__device__ __nv_bfloat16 g_vhi[(size_t)NTOK*KVW];
__device__ __nv_bfloat16 g_vlo[(size_t)NTOK*KVW];

__device__ __nv_bfloat16 g_hid_hi[(size_t)NTOK*DD];
__device__ __nv_bfloat16 g_hid_lo[(size_t)NTOK*DD];
__device__ __nv_bfloat16 g_att_hi[(size_t)NTOK*QW];
__device__ __nv_bfloat16 g_att_lo[(size_t)NTOK*QW];
__device__ __nv_bfloat16 g_wq_hi[(size_t)QW*DD];
__device__ __nv_bfloat16 g_wq_lo[(size_t)QW*DD];
__device__ __nv_bfloat16 g_wk_hi[(size_t)KVW*DD];
__device__ __nv_bfloat16 g_wk_lo[(size_t)KVW*DD];
__device__ __nv_bfloat16 g_wv_hi[(size_t)KVW*DD];
__device__ __nv_bfloat16 g_wv_lo[(size_t)KVW*DD];
__device__ __nv_bfloat16 g_wo_hi[(size_t)DD*QW];
__device__ __nv_bfloat16 g_wo_lo[(size_t)DD*QW];

// ---------------- base-ISA PTX helpers ----------------
__device__ __forceinline__ uint32_t smem_u32(const void* p) {
    uint32_t a;
    asm("{ .reg .u64 t; cvta.to.shared.u64 t, %1; cvt.u32.u64 %0, t; }" : "=r"(a) : "l"(p));
    return a;
}
__device__ __forceinline__ void cp16(uint32_t saddr, const void* g) {
    asm volatile("cp.async.cg.shared.global [%0], [%1], 16;" :: "r"(saddr), "l"(g) : "memory");
}
__device__ __forceinline__ void ldm_x4(uint32_t& r0, uint32_t& r1, uint32_t& r2, uint32_t& r3, uint32_t a) {
    asm volatile("ldmatrix.sync.aligned.m8n8.x4.shared.b16 {%0,%1,%2,%3}, [%4];"
                 : "=r"(r0), "=r"(r1), "=r"(r2), "=r"(r3) : "r"(a));
}
__device__ __forceinline__ void ldm_x4t(uint32_t& r0, uint32_t& r1, uint32_t& r2, uint32_t& r3, uint32_t a) {
    asm volatile("ldmatrix.sync.aligned.m8n8.x4.trans.shared.b16 {%0,%1,%2,%3}, [%4];"
                 : "=r"(r0), "=r"(r1), "=r"(r2), "=r"(r3) : "r"(a));
}
__device__ __forceinline__ void ldm_x2(uint32_t& r0, uint32_t& r1, uint32_t a) {
    asm volatile("ldmatrix.sync.aligned.m8n8.x2.shared.b16 {%0,%1}, [%2];"
                 : "=r"(r0), "=r"(r1) : "r"(a));
}
__device__ __forceinline__ void mma16816(float* d, const uint32_t* a, const uint32_t* b) {
    asm volatile(
        "mma.sync.aligned.m16n8k16.row.col.f32.bf16.bf16.f32 "
        "{%0,%1,%2,%3}, {%4,%5,%6,%7}, {%8,%9}, {%0,%1,%2,%3};"
        : "+f"(d[0]), "+f"(d[1]), "+f"(d[2]), "+f"(d[3])
        : "r"(a[0]), "r"(a[1]), "r"(a[2]), "r"(a[3]), "r"(b[0]), "r"(b[1]));
}
__device__ __forceinline__ uint32_t pkhl(float x, float y) {
    __nv_bfloat162 t = __floats2bfloat162_rn(x, y);
    return *reinterpret_cast<uint32_t*>(&t);
}
__device__ __forceinline__ float bfres(float x) {
    return x - __bfloat162float(__float2bfloat16(x));
}

// ---------------- positions from sorted segment ids ----------------
__global__ void pos_kernel(const int* __restrict__ seg) {
    int idx = blockIdx.x * blockDim.x + threadIdx.x;
    if (idx >= NTOK) return;
    int b = idx / TT, t = idx % TT;
    const int* s = seg + b * TT;
    int v = s[t];
    int lo = 0, hi = t;
    while (lo < hi) { int mid = (lo + hi) >> 1; if (s[mid] < v) lo = mid + 1; else hi = mid; }
    g_pos[idx] = t - lo;
}

// ---------------- elementwise fp32 -> (hi, lo) bf16 split ----------------
__global__ void split_kernel(const float* __restrict__ x,
                             __nv_bfloat16* __restrict__ hi,
                             __nv_bfloat16* __restrict__ lo, int n4) {
    int i = blockIdx.x * blockDim.x + threadIdx.x;
    if (i >= n4) return;
    float4 v = ((const float4*)x)[i];
    __nv_bfloat16 h0 = __float2bfloat16(v.x);
    __nv_bfloat16 h1 = __float2bfloat16(v.y);
    __nv_bfloat16 h2 = __float2bfloat16(v.z);
    __nv_bfloat16 h3 = __float2bfloat16(v.w);
    __nv_bfloat162 ha, hb, la, lb;
    ha.x = h0; ha.y = h1; hb.x = h2; hb.y = h3;
    la.x = __float2bfloat16(v.x - __bfloat162float(h0));
    la.y = __float2bfloat16(v.y - __bfloat162float(h1));
    lb.x = __float2bfloat16(v.z - __bfloat162float(h2));
    lb.y = __float2bfloat16(v.w - __bfloat162float(h3));
    ((__nv_bfloat162*)hi)[2*i] = ha; ((__nv_bfloat162*)hi)[2*i+1] = hb;
    ((__nv_bfloat162*)lo)[2*i] = la; ((__nv_bfloat162*)lo)[2*i+1] = lb;
}

// ---------------- weight transpose + split: W[Rk,N] -> T[N,Rk] hi/lo bf16 -----
__global__ void tsplit_kernel(const float* __restrict__ W,
                              __nv_bfloat16* __restrict__ hi,
                              __nv_bfloat16* __restrict__ lo, int Rk, int N) {
    __shared__ float tile[32][33];
    int tx = threadIdx.x;
    int x = blockIdx.x * 32 + tx;
    int y0 = blockIdx.y * 32;
    for (int i = threadIdx.y; i < 32; i += 8)
        tile[i][tx] = W[(size_t)(y0 + i) * N + x];
    __syncthreads();
    int k = y0 + tx;
    for (int i = threadIdx.y; i < 32; i += 8) {
        int n = blockIdx.x * 32 + i;
        float val = tile[tx][i];
        __nv_bfloat16 h = __float2bfloat16(val);
        hi[(size_t)n * Rk + k] = h;
        lo[(size_t)n * Rk + k] = __float2bfloat16(val - __bfloat162float(h));
    }
}

// ---------------- 3xBF16 GEMM core: 128x128 tile, BK=64, 3-stage pipeline -----
#define ROWB 144                /* 64 bf16 = 128B data + 16B pad */
#define BUFB (128*ROWB)         /* 18432 */
#define GSTAGE (4*BUFB)         /* 73728 */
#define GSM (3*GSTAGE)          /* 221184 */

__device__ __forceinline__ void gemm_core(
    const __nv_bfloat16* __restrict__ Ahi, const __nv_bfloat16* __restrict__ Alo,
    const __nv_bfloat16* __restrict__ Bhi, const __nv_bfloat16* __restrict__ Blo,
    float* __restrict__ C, int Ntot, int Kd, int row0, int col0, char* smbuf)
{
    const int tid = threadIdx.x;
    const int wid = tid >> 5, lane = tid & 31;
    const int warp_m = wid >> 2, warp_n = wid & 3;
    const uint32_t smb = smem_u32(smbuf);

    const __nv_bfloat16* bases[4] = {
        Ahi + (size_t)row0 * Kd, Alo + (size_t)row0 * Kd,
        Bhi + (size_t)col0 * Kd, Blo + (size_t)col0 * Kd };

    float acc[4][4][4];
#pragma unroll
    for (int i = 0; i < 4; i++)
#pragma unroll
        for (int j = 0; j < 4; j++)
#pragma unroll
            for (int c = 0; c < 4; c++) acc[i][j][c] = 0.f;

    const int T = Kd >> 6;

    int ld_buf[16], ld_row[16], ld_c[16];
#pragma unroll
    for (int i = 0; i < 16; i++) {
        int id = tid + (i << 8);
        ld_buf[i] = id >> 10;
        int rem = id & 1023;
        ld_row[i] = rem >> 3;
        ld_c[i] = rem & 7;
    }

#define LOAD_STAGE(t, s) do {                                                   \
    int k0_ = (t) << 6;                                                         \
    _Pragma("unroll")                                                           \
    for (int i_ = 0; i_ < 16; i_++) {                                           \
        uint32_t sa = smb + (s) * GSTAGE + ld_buf[i_] * BUFB +                  \
                      ld_row[i_] * ROWB + ld_c[i_] * 16;                        \
        const __nv_bfloat16* g = bases[ld_buf[i_]] +                            \
            (size_t)ld_row[i_] * Kd + k0_ + ld_c[i_] * 8;                       \
        cp16(sa, g);                                                            \
    }                                                                           \
    asm volatile("cp.async.commit_group;" ::: "memory");                        \
} while (0)

    const uint32_t aoff = (uint32_t)((warp_m * 64 + (lane & 15)) * ROWB + ((lane >> 4) << 3) * 2);
    const uint32_t boff = (uint32_t)((warp_n * 32 + (lane & 7)) * ROWB + (((lane >> 3) & 1) << 3) * 2);

    LOAD_STAGE(0, 0);
    LOAD_STAGE(1, 1);

    for (int t = 0; t < T; t++) {
        int s = t % 3;
        if (t + 2 < T)       asm volatile("cp.async.wait_group 1;" ::: "memory");
        else if (t + 1 < T)  asm volatile("cp.async.wait_group 1;" ::: "memory");
        else                 asm volatile("cp.async.wait_group 0;" ::: "memory");
        __syncthreads();
        if (t + 2 < T) LOAD_STAGE(t + 2, (t + 2) % 3);

        uint32_t stg = smb + s * GSTAGE;
#pragma unroll
        for (int k16 = 0; k16 < 4; k16++) {
            uint32_t aA = stg + aoff + k16 * 32;
            uint32_t bA = stg + 2 * BUFB + boff + k16 * 32;
            uint32_t ah[4][4], al[4][4], bh[4][2], bl[4][2];
#pragma unroll
            for (int mf = 0; mf < 4; mf++) {
                uint32_t ad = aA + mf * 16 * ROWB;
                ldm_x4(ah[mf][0], ah[mf][1], ah[mf][2], ah[mf][3], ad);
                ldm_x4(al[mf][0], al[mf][1], al[mf][2], al[mf][3], ad + BUFB);
            }
#pragma unroll
            for (int nf = 0; nf < 4; nf++) {
                uint32_t bd = bA + nf * 8 * ROWB;
                ldm_x2(bh[nf][0], bh[nf][1], bd);
                ldm_x2(bl[nf][0], bl[nf][1], bd + BUFB);
            }
#pragma unroll
            for (int mf = 0; mf < 4; mf++)
#pragma unroll
                for (int nf = 0; nf < 4; nf++) {
                    mma16816(acc[mf][nf], ah[mf], bh[nf]);
                    mma16816(acc[mf][nf], ah[mf], bl[nf]);
                    mma16816(acc[mf][nf], al[mf], bh[nf]);
                }
        }
    }

    int tr = lane >> 2;
    int tc = (lane & 3) << 1;
#pragma unroll
    for (int mf = 0; mf < 4; mf++) {
        int m = row0 + warp_m * 64 + mf * 16 + tr;
#pragma unroll
        for (int nf = 0; nf < 4; nf++) {
            int n = col0 + warp_n * 32 + nf * 8 + tc;
            *(float2*)(C + (size_t)m * Ntot + n) = make_float2(acc[mf][nf][0], acc[mf][nf][1]);
            *(float2*)(C + (size_t)(m + 8) * Ntot + n) = make_float2(acc[mf][nf][2], acc[mf][nf][3]);
        }
    }
#undef LOAD_STAGE
}

// merged QKV projection: grid.x: 0-15 -> Q, 16-19 -> K, 20-23 -> V
__global__ __launch_bounds__(256, 1) void qkv_gemm_kernel(
    const __nv_bfloat16* __restrict__ Ahi, const __nv_bfloat16* __restrict__ Alo)
{
    extern __shared__ __align__(128) char smbuf[];
    int cx = blockIdx.x;
    const __nv_bfloat16 *Bh, *Bl;
    float* C;
    int Ntot, col0;
    if (cx < 16)      { Bh = g_wq_hi; Bl = g_wq_lo; C = g_q; Ntot = QW;  col0 = cx * 128; }
    else if (cx < 20) { Bh = g_wk_hi; Bl = g_wk_lo; C = g_k; Ntot = KVW; col0 = (cx - 16) * 128; }
    else              { Bh = g_wv_hi; Bl = g_wv_lo; C = g_v; Ntot = KVW; col0 = (cx - 20) * 128; }
    gemm_core(Ahi, Alo, Bh, Bl, C, Ntot, DD, blockIdx.y * 128, col0, smbuf);
}

__global__ __launch_bounds__(256, 1) void mma_gemm_kernel(
    const __nv_bfloat16* __restrict__ Ahi, const __nv_bfloat16* __restrict__ Alo,
    const __nv_bfloat16* __restrict__ Bhi, const __nv_bfloat16* __restrict__ Blo,
    float* __restrict__ C, int Ntot, int Kd)
{
    extern __shared__ __align__(128) char smbuf[];
    gemm_core(Ahi, Alo, Bhi, Blo, C, Ntot, Kd, blockIdx.y * 128, blockIdx.x * 128, smbuf);
}

// ------- fused RMSNorm + RoPE, writes bf16 hi/lo -------
__global__ void normrope_kernel(const float* __restrict__ x, const float* __restrict__ scale,
                                __nv_bfloat16* __restrict__ hi, __nv_bfloat16* __restrict__ lo,
                                int heads) {
    int warp = (blockIdx.x * blockDim.x + threadIdx.x) >> 5;
    int lane = threadIdx.x & 31;
    int token = warp / heads;
    int head = warp % heads;
    const float* p = x + (size_t)token * heads * KKD + head * KKD;

    float4 v = *(const float4*)(p + lane * 4);
    float ss = v.x * v.x + v.y * v.y + v.z * v.z + v.w * v.w;
#pragma unroll
    for (int o = 16; o > 0; o >>= 1) ss += __shfl_xor_sync(0xffffffffu, ss, o);
    float inv = rsqrtf(ss * (1.0f / 128.0f) + 1e-6f);
    float4 sc = *(const float4*)(scale + lane * 4);
    float vv[4];
    vv[0] = v.x * inv * sc.x; vv[1] = v.y * inv * sc.y;
    vv[2] = v.z * inv * sc.z; vv[3] = v.w * inv * sc.w;

    float pf = (float)g_pos[token];
    float out[4];
#pragma unroll
    for (int c = 0; c < 4; c++) {
        int k = lane * 4 + c;
        int j = k & 63;
        float invf = expf(-9.210340371976184f * ((float)j * (1.0f / 64.0f)));
        float sn, cs;
        sincosf(pf * invf, &sn, &cs);
        float partner = __shfl_xor_sync(0xffffffffu, vv[c], 16);
        out[c] = (k < 64) ? (vv[c] * cs - partner * sn) : (vv[c] * cs + partner * sn);
    }
    size_t base = (size_t)token * heads * KKD + head * KKD + lane * 4;
    __nv_bfloat162 h01, h23, l01, l23;
    h01.x = __float2bfloat16(out[0]); h01.y = __float2bfloat16(out[1]);
    h23.x = __float2bfloat16(out[2]); h23.y = __float2bfloat16(out[3]);
    l01.x = __float2bfloat16(out[0] - __bfloat162float(h01.x));
    l01.y = __float2bfloat16(out[1] - __bfloat162float(h01.y));
    l23.x = __float2bfloat16(out[2] - __bfloat162float(h23.x));
    l23.y = __float2bfloat16(out[3] - __bfloat162float(h23.y));
    *(__nv_bfloat162*)(hi + base) = h01; *(__nv_bfloat162*)(hi + base + 2) = h23;
    *(__nv_bfloat162*)(lo + base) = l01; *(__nv_bfloat162*)(lo + base + 2) = l23;
}

// ---------------- tensor-core flash attention, segment-causal -----------------
#define KVSTR 136
#define ABUF (64*KVSTR*2)
#define ATT_SMEM (4*ABUF + 256)

__global__ __launch_bounds__(128) void attn_mma_kernel() {
    extern __shared__ __align__(128) char smraw[];
    char* sQhi = smraw;
    char* sQlo = smraw + ABUF;
    char* sKVhi = smraw + 2 * ABUF;
    char* sKVlo = smraw + 3 * ABUF;
    int* Sst = (int*)(smraw + 4 * ABUF);
    const uint32_t uQhi = smem_u32(sQhi);
    const uint32_t uKVhi = smem_u32(sKVhi);

    const int tid = threadIdx.x;
    const int warp = tid >> 5, lane = tid & 31;
    const int b = blockIdx.z, h = blockIdx.y;
    const int t0 = blockIdx.x * 64;
    const int g = h >> 2;
    const float scale = 0.08838834764831845f;
    const float NEG = -1e30f;

    {
        int r = tid >> 1, half = tid & 1;
        size_t gofs = (size_t)(b * TT + t0 + r) * QW + h * KKD + half * 64;
        const uint4* sh = (const uint4*)(g_qhi + gofs);
        const uint4* sl = (const uint4*)(g_qlo + gofs);
        uint4* dh = (uint4*)(sQhi + (r * KVSTR + half * 64) * 2);
        uint4* dl = (uint4*)(sQlo + (r * KVSTR + half * 64) * 2);
#pragma unroll
        for (int i = 0; i < 8; i++) { dh[i] = sh[i]; dl[i] = sl[i]; }
    }
    if (tid < 64) {
        int t = t0 + tid;
        Sst[tid] = t - g_pos[b * TT + t];
    }
    __syncthreads();

    const int s_begin = Sst[0] & ~63;
    const int r_lo = warp * 16 + (lane >> 2);
    const int t_0 = t0 + r_lo, t_1 = t_0 + 8;
    const int st0 = Sst[r_lo], st1 = Sst[r_lo + 8];
    const int qk = (lane & 3) << 1;

    float m0 = NEG, m1 = NEG, l0 = 0.f, l1 = 0.f;
    float o[16][4];
#pragma unroll
    for (int i = 0; i < 16; i++)
#pragma unroll
        for (int c = 0; c < 4; c++) o[i][c] = 0.f;

    for (int s0 = s_begin; s0 <= t0; s0 += 64) {
        {
            int r = tid >> 1, half = tid & 1;
            size_t gofs = (size_t)(b * TT + s0 + r) * KVW + g * KKD + half * 64;
            const uint4* sh = (const uint4*)(g_khi + gofs);
            const uint4* sl = (const uint4*)(g_klo + gofs);
            uint4* dh = (uint4*)(sKVhi + (r * KVSTR + half * 64) * 2);
            uint4* dl = (uint4*)(sKVlo + (r * KVSTR + half * 64) * 2);
#pragma unroll
            for (int i = 0; i < 8; i++) { dh[i] = sh[i]; dl[i] = sl[i]; }
        }
        __syncthreads();

        float sfr[8][4];
#pragma unroll
        for (int i = 0; i < 8; i++)
#pragma unroll
            for (int c = 0; c < 4; c++) sfr[i][c] = 0.f;

#pragma unroll
        for (int k16 = 0; k16 < 8; k16++) {
            uint32_t qa = uQhi + ((warp * 16 + (lane & 15)) * KVSTR + k16 * 16 + ((lane >> 4) << 3)) * 2;
            uint32_t ah[4], al[4];
            ldm_x4(ah[0], ah[1], ah[2], ah[3], qa);
            ldm_x4(al[0], al[1], al[2], al[3], qa + ABUF);
#pragma unroll
            for (int f = 0; f < 4; f++) {
                uint32_t ka = uKVhi + ((f * 16 + (lane & 7) + ((lane >> 4) << 3)) * KVSTR
                                       + k16 * 16 + (((lane >> 3) & 1) << 3)) * 2;
                uint32_t bh[4], bl[4];
                ldm_x4(bh[0], bh[1], bh[2], bh[3], ka);
                ldm_x4(bl[0], bl[1], bl[2], bl[3], ka + ABUF);
                mma16816(sfr[2*f],   ah, bh);
                mma16816(sfr[2*f],   ah, bl);
                mma16816(sfr[2*f],   al, bh);
                mma16816(sfr[2*f+1], ah, bh + 2);
                mma16816(sfr[2*f+1], ah, bl + 2);
                mma16816(sfr[2*f+1], al, bh + 2);
            }
        }

        float rmax0 = NEG, rmax1 = NEG;
#pragma unroll
        for (int nf = 0; nf < 8; nf++) {
            int c0 = s0 + nf * 8 + qk, c1 = c0 + 1;
            sfr[nf][0] = (c0 <= t_0 && c0 >= st0) ? sfr[nf][0] * scale : NEG;
            sfr[nf][1] = (c1 <= t_0 && c1 >= st0) ? sfr[nf][1] * scale : NEG;
            sfr[nf][2] = (c0 <= t_1 && c0 >= st1) ? sfr[nf][2] * scale : NEG;
            sfr[nf][3] = (c1 <= t_1 && c1 >= st1) ? sfr[nf][3] * scale : NEG;
            rmax0 = fmaxf(rmax0, fmaxf(sfr[nf][0], sfr[nf][1]));
            rmax1 = fmaxf(rmax1, fmaxf(sfr[nf][2], sfr[nf][3]));
        }
        rmax0 = fmaxf(rmax0, __shfl_xor_sync(0xffffffffu, rmax0, 1));
        rmax0 = fmaxf(rmax0, __shfl_xor_sync(0xffffffffu, rmax0, 2));
        rmax1 = fmaxf(rmax1, __shfl_xor_sync(0xffffffffu, rmax1, 1));
        rmax1 = fmaxf(rmax1, __shfl_xor_sync(0xffffffffu, rmax1, 2));

        float mn0 = fmaxf(m0, rmax0), mn1 = fmaxf(m1, rmax1);
        float corr0 = __expf(m0 - mn0), corr1 = __expf(m1 - mn1);
        m0 = mn0; m1 = mn1;
        l0 *= corr0; l1 *= corr1;
#pragma unroll
        for (int i = 0; i < 16; i++) {
            o[i][0] *= corr0; o[i][1] *= corr0;
            o[i][2] *= corr1; o[i][3] *= corr1;
        }
        float sum0 = 0.f, sum1 = 0.f;
#pragma unroll
        for (int nf = 0; nf < 8; nf++) {
            float p0 = (sfr[nf][0] > -5e29f) ? __expf(sfr[nf][0] - mn0) : 0.f;
            float p1 = (sfr[nf][1] > -5e29f) ? __expf(sfr[nf][1] - mn0) : 0.f;
            float p2 = (sfr[nf][2] > -5e29f) ? __expf(sfr[nf][2] - mn1) : 0.f;
            float p3 = (sfr[nf][3] > -5e29f) ? __expf(sfr[nf][3] - mn1) : 0.f;
            sfr[nf][0] = p0; sfr[nf][1] = p1; sfr[nf][2] = p2; sfr[nf][3] = p3;
            sum0 += p0 + p1; sum1 += p2 + p3;
        }
        sum0 += __shfl_xor_sync(0xffffffffu, sum0, 1);
        sum0 += __shfl_xor_sync(0xffffffffu, sum0, 2);
        sum1 += __shfl_xor_sync(0xffffffffu, sum1, 1);
        sum1 += __shfl_xor_sync(0xffffffffu, sum1, 2);
        l0 += sum0; l1 += sum1;

        __syncthreads();

        {
            int r = tid >> 1, half = tid & 1;
            size_t gofs = (size_t)(b * TT + s0 + r) * KVW + g * KKD + half * 64;
            const uint4* sh = (const uint4*)(g_vhi + gofs);
            const uint4* sl = (const uint4*)(g_vlo + gofs);
            uint4* dh = (uint4*)(sKVhi + (r * KVSTR + half * 64) * 2);
            uint4* dl = (uint4*)(sKVlo + (r * KVSTR + half * 64) * 2);
#pragma unroll
            for (int i = 0; i < 8; i++) { dh[i] = sh[i]; dl[i] = sl[i]; }
        }
        __syncthreads();

#pragma unroll
        for (int j = 0; j < 4; j++) {
            uint32_t ph[4], pl[4];
            ph[0] = pkhl(sfr[2*j][0],   sfr[2*j][1]);
            ph[1] = pkhl(sfr[2*j][2],   sfr[2*j][3]);
            ph[2] = pkhl(sfr[2*j+1][0], sfr[2*j+1][1]);
            ph[3] = pkhl(sfr[2*j+1][2], sfr[2*j+1][3]);
            pl[0] = pkhl(bfres(sfr[2*j][0]),   bfres(sfr[2*j][1]));
            pl[1] = pkhl(bfres(sfr[2*j][2]),   bfres(sfr[2*j][3]));
            pl[2] = pkhl(bfres(sfr[2*j+1][0]), bfres(sfr[2*j+1][1]));
            pl[3] = pkhl(bfres(sfr[2*j+1][2]), bfres(sfr[2*j+1][3]));
#pragma unroll
            for (int f = 0; f < 8; f++) {
                uint32_t va = uKVhi + ((j * 16 + (lane & 7) + (((lane >> 3) & 1) << 3)) * KVSTR
                                       + f * 16 + ((lane >> 4) << 3)) * 2;
                uint32_t vh[4], vl[4];
                ldm_x4t(vh[0], vh[1], vh[2], vh[3], va);
                ldm_x4t(vl[0], vl[1], vl[2], vl[3], va + ABUF);
                mma16816(o[2*f],   ph, vh);
                mma16816(o[2*f],   ph, vl);
                mma16816(o[2*f],   pl, vh);
                mma16816(o[2*f+1], ph, vh + 2);
                mma16816(o[2*f+1], ph, vl + 2);
                mma16816(o[2*f+1], pl, vh + 2);
            }
        }
        __syncthreads();
    }

    float inv0 = 1.0f / l0, inv1 = 1.0f / l1;
#pragma unroll
    for (int nf = 0; nf < 16; nf++) {
        int c = h * KKD + nf * 8 + qk;
        size_t a0 = (size_t)(b * TT + t_0) * QW + c;
        size_t a1 = (size_t)(b * TT + t_1) * QW + c;
        float v0 = o[nf][0] * inv0, v1 = o[nf][1] * inv0;
        float v2 = o[nf][2] * inv1, v3 = o[nf][3] * inv1;
        __nv_bfloat162 h0, h1, l0v, l1v;
        h0.x = __float2bfloat16(v0); h0.y = __float2bfloat16(v1);
        h1.x = __float2bfloat16(v2); h1.y = __float2bfloat16(v3);
        l0v.x = __float2bfloat16(v0 - __bfloat162float(h0.x));
        l0v.y = __float2bfloat16(v1 - __bfloat162float(h0.y));
        l1v.x = __float2bfloat16(v2 - __bfloat162float(h1.x));
        l1v.y = __float2bfloat16(v3 - __bfloat162float(h1.y));
        *(__nv_bfloat162*)(g_att_hi + a0) = h0;
        *(__nv_bfloat162*)(g_att_lo + a0) = l0v;
        *(__nv_bfloat162*)(g_att_hi + a1) = h1;
        *(__nv_bfloat162*)(g_att_lo + a1) = l1v;
    }
}

// ---------------- launch ----------------
extern "C" void kernel_launch(void* const* d_in, const int* in_sizes, int n_in,
                              void* d_out, int out_size) {
    const float* hidden  = (const float*)d_in[0];
    const float* wq      = (const float*)d_in[1];
    const float* wk      = (const float*)d_in[2];
    const float* wv      = (const float*)d_in[3];
    const float* wo      = (const float*)d_in[4];
    const float* q_scale = (const float*)d_in[5];
    const float* k_scale = (const float*)d_in[6];
    const int*   seg     = (const int*)d_in[7];
    float* out = (float*)d_out;

    float *q, *k, *v;
    __nv_bfloat16 *hidh, *hidl, *atth, *attl;
    __nv_bfloat16 *qhi, *qlo, *khi, *klo, *vhi, *vlo;
    __nv_bfloat16 *wqh, *wql, *wkh, *wkl, *wvh, *wvl, *woh, *wol;
    cudaGetSymbolAddress((void**)&q, g_q);
    cudaGetSymbolAddress((void**)&k, g_k);
    cudaGetSymbolAddress((void**)&v, g_v);
    cudaGetSymbolAddress((void**)&hidh, g_hid_hi);
    cudaGetSymbolAddress((void**)&hidl, g_hid_lo);
    cudaGetSymbolAddress((void**)&atth, g_att_hi);
    cudaGetSymbolAddress((void**)&attl, g_att_lo);
    cudaGetSymbolAddress((void**)&qhi, g_qhi);
    cudaGetSymbolAddress((void**)&qlo, g_qlo);
    cudaGetSymbolAddress((void**)&khi, g_khi);
    cudaGetSymbolAddress((void**)&klo, g_klo);
    cudaGetSymbolAddress((void**)&vhi, g_vhi);
    cudaGetSymbolAddress((void**)&vlo, g_vlo);
    cudaGetSymbolAddress((void**)&wqh, g_wq_hi);
    cudaGetSymbolAddress((void**)&wql, g_wq_lo);
    cudaGetSymbolAddress((void**)&wkh, g_wk_hi);
    cudaGetSymbolAddress((void**)&wkl, g_wk_lo);
    cudaGetSymbolAddress((void**)&wvh, g_wv_hi);
    cudaGetSymbolAddress((void**)&wvl, g_wv_lo);
    cudaGetSymbolAddress((void**)&woh, g_wo_hi);
    cudaGetSymbolAddress((void**)&wol, g_wo_lo);

    cudaFuncSetAttribute(qkv_gemm_kernel, cudaFuncAttributeMaxDynamicSharedMemorySize, GSM);
    cudaFuncSetAttribute(mma_gemm_kernel, cudaFuncAttributeMaxDynamicSharedMemorySize, GSM);
    cudaFuncSetAttribute(attn_mma_kernel, cudaFuncAttributeMaxDynamicSharedMemorySize, ATT_SMEM);

    // launch order arranged so that ncu (-s 5 -c 1) captures qkv_gemm_kernel (#6)
    pos_kernel<<<NTOK / 256, 256>>>(seg);                                          // 1
    {
        int n4 = NTOK * DD / 4;
        split_kernel<<<(n4 + 255) / 256, 256>>>(hidden, hidh, hidl, n4);           // 2
    }
    tsplit_kernel<<<dim3(QW / 32, DD / 32), dim3(32, 8)>>>(wq, wqh, wql, DD, QW);  // 3
    tsplit_kernel<<<dim3(KVW / 32, DD / 32), dim3(32, 8)>>>(wk, wkh, wkl, DD, KVW);// 4
    tsplit_kernel<<<dim3(KVW / 32, DD / 32), dim3(32, 8)>>>(wv, wvh, wvl, DD, KVW);// 5

    qkv_gemm_kernel<<<dim3(24, NTOK / 128), 256, GSM>>>(hidh, hidl);               // 6 <- profiled

    normrope_kernel<<<(NTOK * HH) / 8, 256>>>(q, q_scale, qhi, qlo, HH);           // 7
    normrope_kernel<<<(NTOK * GG) / 8, 256>>>(k, k_scale, khi, klo, GG);           // 8
    {
        int n4 = NTOK * KVW / 4;
        split_kernel<<<(n4 + 255) / 256, 256>>>(v, vhi, vlo, n4);                  // 9
    }

    attn_mma_kernel<<<dim3(TT / 64, HH, BB), 128, ATT_SMEM>>>();                   // 10

    tsplit_kernel<<<dim3(DD / 32, QW / 32), dim3(32, 8)>>>(wo, woh, wol, QW, DD);  // 11

    mma_gemm_kernel<<<dim3(DD / 128, NTOK / 128), 256, GSM>>>(
        atth, attl, woh, wol, out, DD, QW);                                        // 12
}

// round 8
// speedup vs baseline: 2.5527x; 1.0521x over previous
#include <cuda_runtime.h>
#include <cuda_bf16.h>
#include <math.h>
#include <stdint.h>

#define BB 4
#define TT 2048
#define DD 2048
#define HH 16
#define GG 4
#define KKD 128
#define NTOK (BB*TT)          /* 8192 */
#define QW (HH*KKD)           /* 2048 */
#define KVW (GG*KKD)          /* 512  */

// ---------------- scratch (static device globals; no allocation) ----------------
__device__ float g_q[(size_t)NTOK*QW];
__device__ float g_k[(size_t)NTOK*KVW];
__device__ int   g_pos[NTOK];

__device__ __nv_bfloat16 g_qhi[(size_t)NTOK*QW];
__device__ __nv_bfloat16 g_qlo[(size_t)NTOK*QW];
__device__ __nv_bfloat16 g_khi[(size_t)NTOK*KVW];
__device__ __nv_bfloat16 g_klo[(size_t)NTOK*KVW];
__device__ __nv_bfloat16 g_vhi[(size_t)NTOK*KVW];
__device__ __nv_bfloat16 g_vlo[(size_t)NTOK*KVW];

__device__ __nv_bfloat16 g_hid_hi[(size_t)NTOK*DD];
__device__ __nv_bfloat16 g_hid_lo[(size_t)NTOK*DD];
__device__ __nv_bfloat16 g_att_hi[(size_t)NTOK*QW];
__device__ __nv_bfloat16 g_att_lo[(size_t)NTOK*QW];
__device__ __nv_bfloat16 g_wq_hi[(size_t)QW*DD];
__device__ __nv_bfloat16 g_wq_lo[(size_t)QW*DD];
__device__ __nv_bfloat16 g_wk_hi[(size_t)KVW*DD];
__device__ __nv_bfloat16 g_wk_lo[(size_t)KVW*DD];
__device__ __nv_bfloat16 g_wv_hi[(size_t)KVW*DD];
__device__ __nv_bfloat16 g_wv_lo[(size_t)KVW*DD];
__device__ __nv_bfloat16 g_wo_hi[(size_t)DD*QW];
__device__ __nv_bfloat16 g_wo_lo[(size_t)DD*QW];

// ---------------- base-ISA PTX helpers ----------------
__device__ __forceinline__ uint32_t smem_u32(const void* p) {
    uint32_t a;
    asm("{ .reg .u64 t; cvta.to.shared.u64 t, %1; cvt.u32.u64 %0, t; }" : "=r"(a) : "l"(p));
    return a;
}
__device__ __forceinline__ void cp16(uint32_t saddr, const void* g) {
    asm volatile("cp.async.cg.shared.global [%0], [%1], 16;" :: "r"(saddr), "l"(g) : "memory");
}
__device__ __forceinline__ void ldm_x4(uint32_t& r0, uint32_t& r1, uint32_t& r2, uint32_t& r3, uint32_t a) {
    asm volatile("ldmatrix.sync.aligned.m8n8.x4.shared.b16 {%0,%1,%2,%3}, [%4];"
                 : "=r"(r0), "=r"(r1), "=r"(r2), "=r"(r3) : "r"(a));
}
__device__ __forceinline__ void ldm_x4t(uint32_t& r0, uint32_t& r1, uint32_t& r2, uint32_t& r3, uint32_t a) {
    asm volatile("ldmatrix.sync.aligned.m8n8.x4.trans.shared.b16 {%0,%1,%2,%3}, [%4];"
                 : "=r"(r0), "=r"(r1), "=r"(r2), "=r"(r3) : "r"(a));
}
__device__ __forceinline__ void ldm_x2(uint32_t& r0, uint32_t& r1, uint32_t a) {
    asm volatile("ldmatrix.sync.aligned.m8n8.x2.shared.b16 {%0,%1}, [%2];"
                 : "=r"(r0), "=r"(r1) : "r"(a));
}
__device__ __forceinline__ void mma16816(float* d, const uint32_t* a, const uint32_t* b) {
    asm volatile(
        "mma.sync.aligned.m16n8k16.row.col.f32.bf16.bf16.f32 "
        "{%0,%1,%2,%3}, {%4,%5,%6,%7}, {%8,%9}, {%0,%1,%2,%3};"
        : "+f"(d[0]), "+f"(d[1]), "+f"(d[2]), "+f"(d[3])
        : "r"(a[0]), "r"(a[1]), "r"(a[2]), "r"(a[3]), "r"(b[0]), "r"(b[1]));
}
__device__ __forceinline__ uint32_t pkhl(float x, float y) {
    __nv_bfloat162 t = __floats2bfloat162_rn(x, y);
    return *reinterpret_cast<uint32_t*>(&t);
}
__device__ __forceinline__ float bfres(float x) {
    return x - __bfloat162float(__float2bfloat16(x));
}

// ---------------- positions from sorted segment ids ----------------
__global__ void pos_kernel(const int* __restrict__ seg) {
    int idx = blockIdx.x * blockDim.x + threadIdx.x;
    if (idx >= NTOK) return;
    int b = idx / TT, t = idx % TT;
    const int* s = seg + b * TT;
    int v = s[t];
    int lo = 0, hi = t;
    while (lo < hi) { int mid = (lo + hi) >> 1; if (s[mid] < v) lo = mid + 1; else hi = mid; }
    g_pos[idx] = t - lo;
}

// ---------------- elementwise fp32 -> (hi, lo) bf16 split ----------------
__global__ void split_kernel(const float* __restrict__ x,
                             __nv_bfloat16* __restrict__ hi,
                             __nv_bfloat16* __restrict__ lo, int n4) {
    int i = blockIdx.x * blockDim.x + threadIdx.x;
    if (i >= n4) return;
    float4 v = ((const float4*)x)[i];
    __nv_bfloat16 h0 = __float2bfloat16(v.x);
    __nv_bfloat16 h1 = __float2bfloat16(v.y);
    __nv_bfloat16 h2 = __float2bfloat16(v.z);
    __nv_bfloat16 h3 = __float2bfloat16(v.w);
    __nv_bfloat162 ha, hb, la, lb;
    ha.x = h0; ha.y = h1; hb.x = h2; hb.y = h3;
    la.x = __float2bfloat16(v.x - __bfloat162float(h0));
    la.y = __float2bfloat16(v.y - __bfloat162float(h1));
    lb.x = __float2bfloat16(v.z - __bfloat162float(h2));
    lb.y = __float2bfloat16(v.w - __bfloat162float(h3));
    ((__nv_bfloat162*)hi)[2*i] = ha; ((__nv_bfloat162*)hi)[2*i+1] = hb;
    ((__nv_bfloat162*)lo)[2*i] = la; ((__nv_bfloat162*)lo)[2*i+1] = lb;
}

// ---------------- weight transpose + split: W[Rk,N] -> T[N,Rk] hi/lo bf16 -----
__global__ void tsplit_kernel(const float* __restrict__ W,
                              __nv_bfloat16* __restrict__ hi,
                              __nv_bfloat16* __restrict__ lo, int Rk, int N) {
    __shared__ float tile[32][33];
    int tx = threadIdx.x;
    int x = blockIdx.x * 32 + tx;
    int y0 = blockIdx.y * 32;
    for (int i = threadIdx.y; i < 32; i += 8)
        tile[i][tx] = W[(size_t)(y0 + i) * N + x];
    __syncthreads();
    int k = y0 + tx;
    for (int i = threadIdx.y; i < 32; i += 8) {
        int n = blockIdx.x * 32 + i;
        float val = tile[tx][i];
        __nv_bfloat16 h = __float2bfloat16(val);
        hi[(size_t)n * Rk + k] = h;
        lo[(size_t)n * Rk + k] = __float2bfloat16(val - __bfloat162float(h));
    }
}

// ---------------- 3xBF16 GEMM core: 128x128 tile, BK=64, 3-stage pipeline -----
#define ROWB 144                /* 64 bf16 = 128B data + 16B pad */
#define BUFB (128*ROWB)         /* 18432 */
#define GSTAGE (4*BUFB)         /* 73728 */
#define GSM (3*GSTAGE)          /* 221184 */

__device__ __forceinline__ void gemm_core(
    const __nv_bfloat16* __restrict__ Ahi, const __nv_bfloat16* __restrict__ Alo,
    const __nv_bfloat16* __restrict__ Bhi, const __nv_bfloat16* __restrict__ Blo,
    float* __restrict__ C, __nv_bfloat16* __restrict__ Chi, __nv_bfloat16* __restrict__ Clo,
    int mode, int Ntot, int Kd, int row0, int col0, char* smbuf)
{
    const int tid = threadIdx.x;
    const int wid = tid >> 5, lane = tid & 31;
    const int warp_m = wid >> 2, warp_n = wid & 3;
    const uint32_t smb = smem_u32(smbuf);

    const __nv_bfloat16* bases[4] = {
        Ahi + (size_t)row0 * Kd, Alo + (size_t)row0 * Kd,
        Bhi + (size_t)col0 * Kd, Blo + (size_t)col0 * Kd };

    float acc[4][4][4];
#pragma unroll
    for (int i = 0; i < 4; i++)
#pragma unroll
        for (int j = 0; j < 4; j++)
#pragma unroll
            for (int c = 0; c < 4; c++) acc[i][j][c] = 0.f;

    const int T = Kd >> 6;

    int ld_buf[16], ld_row[16], ld_c[16];
#pragma unroll
    for (int i = 0; i < 16; i++) {
        int id = tid + (i << 8);
        ld_buf[i] = id >> 10;
        int rem = id & 1023;
        ld_row[i] = rem >> 3;
        ld_c[i] = rem & 7;
    }

#define LOAD_STAGE(t, s) do {                                                   \
    int k0_ = (t) << 6;                                                         \
    _Pragma("unroll")                                                           \
    for (int i_ = 0; i_ < 16; i_++) {                                           \
        uint32_t sa = smb + (s) * GSTAGE + ld_buf[i_] * BUFB +                  \
                      ld_row[i_] * ROWB + ld_c[i_] * 16;                        \
        const __nv_bfloat16* g = bases[ld_buf[i_]] +                            \
            (size_t)ld_row[i_] * Kd + k0_ + ld_c[i_] * 8;                       \
        cp16(sa, g);                                                            \
    }                                                                           \
    asm volatile("cp.async.commit_group;" ::: "memory");                        \
} while (0)

    const uint32_t aoff = (uint32_t)((warp_m * 64 + (lane & 15)) * ROWB + ((lane >> 4) << 3) * 2);
    const uint32_t boff = (uint32_t)((warp_n * 32 + (lane & 7)) * ROWB + (((lane >> 3) & 1) << 3) * 2);

    LOAD_STAGE(0, 0);
    LOAD_STAGE(1, 1);

    for (int t = 0; t < T; t++) {
        int s = t % 3;
        if (t + 1 < T)  asm volatile("cp.async.wait_group 1;" ::: "memory");
        else            asm volatile("cp.async.wait_group 0;" ::: "memory");
        __syncthreads();
        if (t + 2 < T) LOAD_STAGE(t + 2, (t + 2) % 3);

        uint32_t stg = smb + s * GSTAGE;
#pragma unroll
        for (int k16 = 0; k16 < 4; k16++) {
            uint32_t aA = stg + aoff + k16 * 32;
            uint32_t bA = stg + 2 * BUFB + boff + k16 * 32;
            uint32_t ah[4][4], al[4][4], bh[4][2], bl[4][2];
#pragma unroll
            for (int mf = 0; mf < 4; mf++) {
                uint32_t ad = aA + mf * 16 * ROWB;
                ldm_x4(ah[mf][0], ah[mf][1], ah[mf][2], ah[mf][3], ad);
                ldm_x4(al[mf][0], al[mf][1], al[mf][2], al[mf][3], ad + BUFB);
            }
#pragma unroll
            for (int nf = 0; nf < 4; nf++) {
                uint32_t bd = bA + nf * 8 * ROWB;
                ldm_x2(bh[nf][0], bh[nf][1], bd);
                ldm_x2(bl[nf][0], bl[nf][1], bd + BUFB);
            }
#pragma unroll
            for (int mf = 0; mf < 4; mf++)
#pragma unroll
                for (int nf = 0; nf < 4; nf++) {
                    mma16816(acc[mf][nf], ah[mf], bh[nf]);
                    mma16816(acc[mf][nf], ah[mf], bl[nf]);
                    mma16816(acc[mf][nf], al[mf], bh[nf]);
                }
        }
    }

    int tr = lane >> 2;
    int tc = (lane & 3) << 1;
    if (mode == 0) {
#pragma unroll
        for (int mf = 0; mf < 4; mf++) {
            int m = row0 + warp_m * 64 + mf * 16 + tr;
#pragma unroll
            for (int nf = 0; nf < 4; nf++) {
                int n = col0 + warp_n * 32 + nf * 8 + tc;
                *(float2*)(C + (size_t)m * Ntot + n) = make_float2(acc[mf][nf][0], acc[mf][nf][1]);
                *(float2*)(C + (size_t)(m + 8) * Ntot + n) = make_float2(acc[mf][nf][2], acc[mf][nf][3]);
            }
        }
    } else {
#pragma unroll
        for (int mf = 0; mf < 4; mf++) {
            int m = row0 + warp_m * 64 + mf * 16 + tr;
#pragma unroll
            for (int nf = 0; nf < 4; nf++) {
                int n = col0 + warp_n * 32 + nf * 8 + tc;
#pragma unroll
                for (int rr = 0; rr < 2; rr++) {
                    float v0 = acc[mf][nf][rr*2], v1 = acc[mf][nf][rr*2+1];
                    __nv_bfloat162 hh, ll;
                    hh.x = __float2bfloat16(v0); hh.y = __float2bfloat16(v1);
                    ll.x = __float2bfloat16(v0 - __bfloat162float(hh.x));
                    ll.y = __float2bfloat16(v1 - __bfloat162float(hh.y));
                    size_t a = (size_t)(m + rr*8) * Ntot + n;
                    *(__nv_bfloat162*)(Chi + a) = hh;
                    *(__nv_bfloat162*)(Clo + a) = ll;
                }
            }
        }
    }
#undef LOAD_STAGE
}

// merged QKV projection: grid.x: 0-15 -> Q, 16-19 -> K, 20-23 -> V (V writes hi/lo)
__global__ __launch_bounds__(256, 1) void qkv_gemm_kernel(
    const __nv_bfloat16* __restrict__ Ahi, const __nv_bfloat16* __restrict__ Alo)
{
    extern __shared__ __align__(128) char smbuf[];
    int cx = blockIdx.x;
    if (cx < 16) {
        gemm_core(Ahi, Alo, g_wq_hi, g_wq_lo, g_q, 0, 0, 0, QW, DD,
                  blockIdx.y * 128, cx * 128, smbuf);
    } else if (cx < 20) {
        gemm_core(Ahi, Alo, g_wk_hi, g_wk_lo, g_k, 0, 0, 0, KVW, DD,
                  blockIdx.y * 128, (cx - 16) * 128, smbuf);
    } else {
        gemm_core(Ahi, Alo, g_wv_hi, g_wv_lo, 0, g_vhi, g_vlo, 1, KVW, DD,
                  blockIdx.y * 128, (cx - 20) * 128, smbuf);
    }
}

__global__ __launch_bounds__(256, 1) void mma_gemm_kernel(
    const __nv_bfloat16* __restrict__ Ahi, const __nv_bfloat16* __restrict__ Alo,
    const __nv_bfloat16* __restrict__ Bhi, const __nv_bfloat16* __restrict__ Blo,
    float* __restrict__ C, int Ntot, int Kd)
{
    extern __shared__ __align__(128) char smbuf[];
    gemm_core(Ahi, Alo, Bhi, Blo, C, 0, 0, 0, Ntot, Kd,
              blockIdx.y * 128, blockIdx.x * 128, smbuf);
}

// ------- fused RMSNorm + RoPE, writes bf16 hi/lo -------
__global__ void normrope_kernel(const float* __restrict__ x, const float* __restrict__ scale,
                                __nv_bfloat16* __restrict__ hi, __nv_bfloat16* __restrict__ lo,
                                int heads) {
    int warp = (blockIdx.x * blockDim.x + threadIdx.x) >> 5;
    int lane = threadIdx.x & 31;
    int token = warp / heads;
    int head = warp % heads;
    const float* p = x + (size_t)token * heads * KKD + head * KKD;

    float4 v = *(const float4*)(p + lane * 4);
    float ss = v.x * v.x + v.y * v.y + v.z * v.z + v.w * v.w;
#pragma unroll
    for (int o = 16; o > 0; o >>= 1) ss += __shfl_xor_sync(0xffffffffu, ss, o);
    float inv = rsqrtf(ss * (1.0f / 128.0f) + 1e-6f);
    float4 sc = *(const float4*)(scale + lane * 4);
    float vv[4];
    vv[0] = v.x * inv * sc.x; vv[1] = v.y * inv * sc.y;
    vv[2] = v.z * inv * sc.z; vv[3] = v.w * inv * sc.w;

    float pf = (float)g_pos[token];
    float out[4];
#pragma unroll
    for (int c = 0; c < 4; c++) {
        int k = lane * 4 + c;
        int j = k & 63;
        float invf = expf(-9.210340371976184f * ((float)j * (1.0f / 64.0f)));
        float sn, cs;
        sincosf(pf * invf, &sn, &cs);
        float partner = __shfl_xor_sync(0xffffffffu, vv[c], 16);
        out[c] = (k < 64) ? (vv[c] * cs - partner * sn) : (vv[c] * cs + partner * sn);
    }
    size_t base = (size_t)token * heads * KKD + head * KKD + lane * 4;
    __nv_bfloat162 h01, h23, l01, l23;
    h01.x = __float2bfloat16(out[0]); h01.y = __float2bfloat16(out[1]);
    h23.x = __float2bfloat16(out[2]); h23.y = __float2bfloat16(out[3]);
    l01.x = __float2bfloat16(out[0] - __bfloat162float(h01.x));
    l01.y = __float2bfloat16(out[1] - __bfloat162float(h01.y));
    l23.x = __float2bfloat16(out[2] - __bfloat162float(h23.x));
    l23.y = __float2bfloat16(out[3] - __bfloat162float(h23.y));
    *(__nv_bfloat162*)(hi + base) = h01; *(__nv_bfloat162*)(hi + base + 2) = h23;
    *(__nv_bfloat162*)(lo + base) = l01; *(__nv_bfloat162*)(lo + base + 2) = l23;
}

// ---------------- tensor-core flash attention, 2 heads per CTA ----------------
// BM=64, D=128, 256 threads (8 warps): warps 0-3 head h0, warps 4-7 head h1.
// Heads 2p, 2p+1 share the same GQA group (R=4), so K/V tiles are shared.
#define KVSTR 136
#define ABUF (64*KVSTR*2)                  /* 17408 B */
#define ATT_SMEM (6*ABUF + 256)            /* Qhi/lo x2 heads + KVhi/lo + Sst */

__global__ __launch_bounds__(256) void attn_mma_kernel() {
    extern __shared__ __align__(128) char smraw[];
    char* sQ = smraw;                       // [head][hi,lo] each ABUF
    char* sKVhi = smraw + 4 * ABUF;
    char* sKVlo = smraw + 5 * ABUF;
    int* Sst = (int*)(smraw + 6 * ABUF);
    const uint32_t uKVhi = smem_u32(sKVhi);

    const int tid = threadIdx.x;
    const int warp = tid >> 5, lane = tid & 31;
    const int b = blockIdx.z;
    const int h0 = blockIdx.y * 2;
    const int hsub = warp >> 2;
    const int h = h0 + hsub;
    const int w4 = warp & 3;
    const int t0 = blockIdx.x * 64;
    const int g = h0 >> 2;
    const float scale = 0.08838834764831845f;
    const float NEG = -1e30f;

    const uint32_t uQ = smem_u32(sQ) + hsub * 2 * ABUF;

    // load Q tiles for both heads: tid>>7 selects head
    {
        int hsel = tid >> 7;
        int r = (tid >> 1) & 63, half = tid & 1;
        size_t gofs = (size_t)(b * TT + t0 + r) * QW + (h0 + hsel) * KKD + half * 64;
        const uint4* sh = (const uint4*)(g_qhi + gofs);
        const uint4* sl = (const uint4*)(g_qlo + gofs);
        char* dh = sQ + hsel * 2 * ABUF + (r * KVSTR + half * 64) * 2;
#pragma unroll
        for (int i = 0; i < 8; i++) {
            ((uint4*)dh)[i] = sh[i];
            ((uint4*)(dh + ABUF))[i] = sl[i];
        }
    }
    if (tid < 64) {
        int t = t0 + tid;
        Sst[tid] = t - g_pos[b * TT + t];
    }
    __syncthreads();

    const int s_begin = Sst[0] & ~63;
    const int r_lo = w4 * 16 + (lane >> 2);
    const int t_0 = t0 + r_lo, t_1 = t_0 + 8;
    const int st0 = Sst[r_lo], st1 = Sst[r_lo + 8];
    const int qk = (lane & 3) << 1;

    float m0 = NEG, m1 = NEG, l0 = 0.f, l1 = 0.f;
    float o[16][4];
#pragma unroll
    for (int i = 0; i < 16; i++)
#pragma unroll
        for (int c = 0; c < 4; c++) o[i][c] = 0.f;

    for (int s0 = s_begin; s0 <= t0; s0 += 64) {
        // ---- load K tile hi/lo: 4 threads per row, 32 bf16 (4x uint4) each ----
        {
            int r = tid >> 2, q4 = tid & 3;
            size_t gofs = (size_t)(b * TT + s0 + r) * KVW + g * KKD + q4 * 32;
            const uint4* sh = (const uint4*)(g_khi + gofs);
            const uint4* sl = (const uint4*)(g_klo + gofs);
            char* dh = sKVhi + (r * KVSTR + q4 * 32) * 2;
#pragma unroll
            for (int i = 0; i < 4; i++) {
                ((uint4*)dh)[i] = sh[i];
                ((uint4*)(dh + ABUF))[i] = sl[i];
            }
        }
        __syncthreads();

        // ---- S = Q K^T (3xBF16) ----
        float sfr[8][4];
#pragma unroll
        for (int i = 0; i < 8; i++)
#pragma unroll
            for (int c = 0; c < 4; c++) sfr[i][c] = 0.f;

#pragma unroll
        for (int k16 = 0; k16 < 8; k16++) {
            uint32_t qa = uQ + ((w4 * 16 + (lane & 15)) * KVSTR + k16 * 16 + ((lane >> 4) << 3)) * 2;
            uint32_t ah[4], al[4];
            ldm_x4(ah[0], ah[1], ah[2], ah[3], qa);
            ldm_x4(al[0], al[1], al[2], al[3], qa + ABUF);
#pragma unroll
            for (int f = 0; f < 4; f++) {
                uint32_t ka = uKVhi + ((f * 16 + (lane & 7) + ((lane >> 4) << 3)) * KVSTR
                                       + k16 * 16 + (((lane >> 3) & 1) << 3)) * 2;
                uint32_t bh[4], bl[4];
                ldm_x4(bh[0], bh[1], bh[2], bh[3], ka);
                ldm_x4(bl[0], bl[1], bl[2], bl[3], ka + ABUF);
                mma16816(sfr[2*f],   ah, bh);
                mma16816(sfr[2*f],   ah, bl);
                mma16816(sfr[2*f],   al, bh);
                mma16816(sfr[2*f+1], ah, bh + 2);
                mma16816(sfr[2*f+1], ah, bl + 2);
                mma16816(sfr[2*f+1], al, bh + 2);
            }
        }

        // ---- mask + online softmax ----
        float rmax0 = NEG, rmax1 = NEG;
#pragma unroll
        for (int nf = 0; nf < 8; nf++) {
            int c0 = s0 + nf * 8 + qk, c1 = c0 + 1;
            sfr[nf][0] = (c0 <= t_0 && c0 >= st0) ? sfr[nf][0] * scale : NEG;
            sfr[nf][1] = (c1 <= t_0 && c1 >= st0) ? sfr[nf][1] * scale : NEG;
            sfr[nf][2] = (c0 <= t_1 && c0 >= st1) ? sfr[nf][2] * scale : NEG;
            sfr[nf][3] = (c1 <= t_1 && c1 >= st1) ? sfr[nf][3] * scale : NEG;
            rmax0 = fmaxf(rmax0, fmaxf(sfr[nf][0], sfr[nf][1]));
            rmax1 = fmaxf(rmax1, fmaxf(sfr[nf][2], sfr[nf][3]));
        }
        rmax0 = fmaxf(rmax0, __shfl_xor_sync(0xffffffffu, rmax0, 1));
        rmax0 = fmaxf(rmax0, __shfl_xor_sync(0xffffffffu, rmax0, 2));
        rmax1 = fmaxf(rmax1, __shfl_xor_sync(0xffffffffu, rmax1, 1));
        rmax1 = fmaxf(rmax1, __shfl_xor_sync(0xffffffffu, rmax1, 2));

        float mn0 = fmaxf(m0, rmax0), mn1 = fmaxf(m1, rmax1);
        float corr0 = __expf(m0 - mn0), corr1 = __expf(m1 - mn1);
        m0 = mn0; m1 = mn1;
        l0 *= corr0; l1 *= corr1;
#pragma unroll
        for (int i = 0; i < 16; i++) {
            o[i][0] *= corr0; o[i][1] *= corr0;
            o[i][2] *= corr1; o[i][3] *= corr1;
        }
        float sum0 = 0.f, sum1 = 0.f;
#pragma unroll
        for (int nf = 0; nf < 8; nf++) {
            float p0 = (sfr[nf][0] > -5e29f) ? __expf(sfr[nf][0] - mn0) : 0.f;
            float p1 = (sfr[nf][1] > -5e29f) ? __expf(sfr[nf][1] - mn0) : 0.f;
            float p2 = (sfr[nf][2] > -5e29f) ? __expf(sfr[nf][2] - mn1) : 0.f;
            float p3 = (sfr[nf][3] > -5e29f) ? __expf(sfr[nf][3] - mn1) : 0.f;
            sfr[nf][0] = p0; sfr[nf][1] = p1; sfr[nf][2] = p2; sfr[nf][3] = p3;
            sum0 += p0 + p1; sum1 += p2 + p3;
        }
        sum0 += __shfl_xor_sync(0xffffffffu, sum0, 1);
        sum0 += __shfl_xor_sync(0xffffffffu, sum0, 2);
        sum1 += __shfl_xor_sync(0xffffffffu, sum1, 1);
        sum1 += __shfl_xor_sync(0xffffffffu, sum1, 2);
        l0 += sum0; l1 += sum1;

        __syncthreads();

        // ---- load V tile hi/lo: 4 threads per row, 32 bf16 (4x uint4) each ----
        {
            int r = tid >> 2, q4 = tid & 3;
            size_t gofs = (size_t)(b * TT + s0 + r) * KVW + g * KKD + q4 * 32;
            const uint4* sh = (const uint4*)(g_vhi + gofs);
            const uint4* sl = (const uint4*)(g_vlo + gofs);
            char* dh = sKVhi + (r * KVSTR + q4 * 32) * 2;
#pragma unroll
            for (int i = 0; i < 4; i++) {
                ((uint4*)dh)[i] = sh[i];
                ((uint4*)(dh + ABUF))[i] = sl[i];
            }
        }
        __syncthreads();

        // ---- O += P V (3xBF16) ----
#pragma unroll
        for (int j = 0; j < 4; j++) {
            uint32_t ph[4], pl[4];
            ph[0] = pkhl(sfr[2*j][0],   sfr[2*j][1]);
            ph[1] = pkhl(sfr[2*j][2],   sfr[2*j][3]);
            ph[2] = pkhl(sfr[2*j+1][0], sfr[2*j+1][1]);
            ph[3] = pkhl(sfr[2*j+1][2], sfr[2*j+1][3]);
            pl[0] = pkhl(bfres(sfr[2*j][0]),   bfres(sfr[2*j][1]));
            pl[1] = pkhl(bfres(sfr[2*j][2]),   bfres(sfr[2*j][3]));
            pl[2] = pkhl(bfres(sfr[2*j+1][0]), bfres(sfr[2*j+1][1]));
            pl[3] = pkhl(bfres(sfr[2*j+1][2]), bfres(sfr[2*j+1][3]));
#pragma unroll
            for (int f = 0; f < 8; f++) {
                uint32_t va = uKVhi + ((j * 16 + (lane & 7) + (((lane >> 3) & 1) << 3)) * KVSTR
                                       + f * 16 + ((lane >> 4) << 3)) * 2;
                uint32_t vh[4], vl[4];
                ldm_x4t(vh[0], vh[1], vh[2], vh[3], va);
                ldm_x4t(vl[0], vl[1], vl[2], vl[3], va + ABUF);
                mma16816(o[2*f],   ph, vh);
                mma16816(o[2*f],   ph, vl);
                mma16816(o[2*f],   pl, vh);
                mma16816(o[2*f+1], ph, vh + 2);
                mma16816(o[2*f+1], ph, vl + 2);
                mma16816(o[2*f+1], pl, vh + 2);
            }
        }
        __syncthreads();
    }

    // ---- epilogue ----
    float inv0 = 1.0f / l0, inv1 = 1.0f / l1;
#pragma unroll
    for (int nf = 0; nf < 16; nf++) {
        int c = h * KKD + nf * 8 + qk;
        size_t a0 = (size_t)(b * TT + t_0) * QW + c;
        size_t a1 = (size_t)(b * TT + t_1) * QW + c;
        float v0 = o[nf][0] * inv0, v1 = o[nf][1] * inv0;
        float v2 = o[nf][2] * inv1, v3 = o[nf][3] * inv1;
        __nv_bfloat162 hh0, hh1, ll0, ll1;
        hh0.x = __float2bfloat16(v0); hh0.y = __float2bfloat16(v1);
        hh1.x = __float2bfloat16(v2); hh1.y = __float2bfloat16(v3);
        ll0.x = __float2bfloat16(v0 - __bfloat162float(hh0.x));
        ll0.y = __float2bfloat16(v1 - __bfloat162float(hh0.y));
        ll1.x = __float2bfloat16(v2 - __bfloat162float(hh1.x));
        ll1.y = __float2bfloat16(v3 - __bfloat162float(hh1.y));
        *(__nv_bfloat162*)(g_att_hi + a0) = hh0;
        *(__nv_bfloat162*)(g_att_lo + a0) = ll0;
        *(__nv_bfloat162*)(g_att_hi + a1) = hh1;
        *(__nv_bfloat162*)(g_att_lo + a1) = ll1;
    }
}

// ---------------- launch ----------------
extern "C" void kernel_launch(void* const* d_in, const int* in_sizes, int n_in,
                              void* d_out, int out_size) {
    const float* hidden  = (const float*)d_in[0];
    const float* wq      = (const float*)d_in[1];
    const float* wk      = (const float*)d_in[2];
    const float* wv      = (const float*)d_in[3];
    const float* wo      = (const float*)d_in[4];
    const float* q_scale = (const float*)d_in[5];
    const float* k_scale = (const float*)d_in[6];
    const int*   seg     = (const int*)d_in[7];
    float* out = (float*)d_out;

    float *q, *k;
    __nv_bfloat16 *hidh, *hidl, *atth, *attl;
    __nv_bfloat16 *qhi, *qlo, *khi, *klo;
    __nv_bfloat16 *wqh, *wql, *wkh, *wkl, *wvh, *wvl, *woh, *wol;
    cudaGetSymbolAddress((void**)&q, g_q);
    cudaGetSymbolAddress((void**)&k, g_k);
    cudaGetSymbolAddress((void**)&hidh, g_hid_hi);
    cudaGetSymbolAddress((void**)&hidl, g_hid_lo);
    cudaGetSymbolAddress((void**)&atth, g_att_hi);
    cudaGetSymbolAddress((void**)&attl, g_att_lo);
    cudaGetSymbolAddress((void**)&qhi, g_qhi);
    cudaGetSymbolAddress((void**)&qlo, g_qlo);
    cudaGetSymbolAddress((void**)&khi, g_khi);
    cudaGetSymbolAddress((void**)&klo, g_klo);
    cudaGetSymbolAddress((void**)&wqh, g_wq_hi);
    cudaGetSymbolAddress((void**)&wql, g_wq_lo);
    cudaGetSymbolAddress((void**)&wkh, g_wk_hi);
    cudaGetSymbolAddress((void**)&wkl, g_wk_lo);
    cudaGetSymbolAddress((void**)&wvh, g_wv_hi);
    cudaGetSymbolAddress((void**)&wvl, g_wv_lo);
    cudaGetSymbolAddress((void**)&woh, g_wo_hi);
    cudaGetSymbolAddress((void**)&wol, g_wo_lo);

    cudaFuncSetAttribute(qkv_gemm_kernel, cudaFuncAttributeMaxDynamicSharedMemorySize, GSM);
    cudaFuncSetAttribute(mma_gemm_kernel, cudaFuncAttributeMaxDynamicSharedMemorySize, GSM);
    cudaFuncSetAttribute(attn_mma_kernel, cudaFuncAttributeMaxDynamicSharedMemorySize, ATT_SMEM);

    pos_kernel<<<NTOK / 256, 256>>>(seg);                                          // 1
    {
        int n4 = NTOK * DD / 4;
        split_kernel<<<(n4 + 255) / 256, 256>>>(hidden, hidh, hidl, n4);           // 2
    }
    tsplit_kernel<<<dim3(QW / 32, DD / 32), dim3(32, 8)>>>(wq, wqh, wql, DD, QW);  // 3
    tsplit_kernel<<<dim3(KVW / 32, DD / 32), dim3(32, 8)>>>(wk, wkh, wkl, DD, KVW);// 4
    tsplit_kernel<<<dim3(KVW / 32, DD / 32), dim3(32, 8)>>>(wv, wvh, wvl, DD, KVW);// 5

    qkv_gemm_kernel<<<dim3(24, NTOK / 128), 256, GSM>>>(hidh, hidl);               // 6

    normrope_kernel<<<(NTOK * HH) / 8, 256>>>(q, q_scale, qhi, qlo, HH);           // 7
    normrope_kernel<<<(NTOK * GG) / 8, 256>>>(k, k_scale, khi, klo, GG);           // 8

    attn_mma_kernel<<<dim3(TT / 64, HH / 2, BB), 256, ATT_SMEM>>>();               // 9

    tsplit_kernel<<<dim3(DD / 32, QW / 32), dim3(32, 8)>>>(wo, woh, wol, QW, DD);  // 10

    mma_gemm_kernel<<<dim3(DD / 128, NTOK / 128), 256, GSM>>>(
        atth, attl, woh, wol, out, DD, QW);                                        // 11
}